// round 9
// baseline (speedup 1.0000x reference)
#include <cuda_runtime.h>
#include <math.h>

#define DIMC   1024
#define NHEADS 16
#define HDIM   64
#define BATCH  4
#define NQ     4096
#define NCTX   256

// Scratch (no allocations allowed) ------------------------------------------
__device__ float g_q [BATCH * NQ   * DIMC];  // 64 MB
__device__ float g_k [BATCH * NCTX * DIMC];  //  4 MB
__device__ float g_v [BATCH * NCTX * DIMC];  //  4 MB
__device__ float g_ao[BATCH * NQ   * DIMC];  // 64 MB

// ===========================================================================
// tf32 tensor-core GEMM: C[M,N] = A[M,K] @ B[K,N] (+bias)
// 128x128x32 CTA tile, 256 threads (2x4 warps, warp tile 64x32),
// mma.sync.aligned.m16n8k8.row.col.f32.tf32.tf32.f32, fp32 accumulate.
// smem: A [128][36] (rows 144B, 16B-aligned; frag reads conflict-free),
//       B [32][132] (rows 528B, 16B-aligned; frag reads <=2-way).
// Double-buffered cp.async.cg 16B pipeline.
// blockIdx.z selects (B0,C0) vs (B1,C1) so K and V proj share one launch.
// ===========================================================================
#define AST 36
#define BST 132
#define STAGE_F (128 * AST + 32 * BST)   // floats per stage = 8832
#define STAGE_B (STAGE_F * 4)            // 35328 bytes
#define GEMM_SMEM (2 * STAGE_B)          // 70656 bytes

__device__ __forceinline__ unsigned f2tf(float f) {
    unsigned r;
    asm("cvt.rna.tf32.f32 %0, %1;" : "=r"(r) : "f"(f));
    return r;
}

#define CPA16(saddr, gptr) \
    asm volatile("cp.async.cg.shared.global [%0], [%1], 16;" :: "r"(saddr), "l"(gptr))

__global__ __launch_bounds__(256) void gemm_tf32(
    const float* __restrict__ A,
    const float* __restrict__ B0, const float* __restrict__ B1,
    const float* __restrict__ bias,
    float* __restrict__ C0, float* __restrict__ C1,
    int M, int N, int K)
{
    extern __shared__ float sh[];
    const float* Bg = (blockIdx.z == 0) ? B0 : B1;
    float*       C  = (blockIdx.z == 0) ? C0 : C1;

    const int t    = threadIdx.x;
    const int lane = t & 31;
    const int w    = t >> 5;
    const int wm   = (w & 1) * 64;
    const int wn   = (w >> 1) * 32;
    const int m0   = blockIdx.y * 128;
    const int n0   = blockIdx.x * 128;

    const unsigned shu = (unsigned)__cvta_generic_to_shared(sh);

    float acc[4][4][4];
#pragma unroll
    for (int mt = 0; mt < 4; mt++)
#pragma unroll
        for (int nt = 0; nt < 4; nt++)
#pragma unroll
            for (int i = 0; i < 4; i++) acc[mt][nt][i] = 0.f;

    // ---- async load of one stage -----------------------------------------
    // A tile: 128 rows x 32 cols -> 1024 float4, 4 per thread
    // B tile:  32 rows x 128 cols -> 1024 float4, 4 per thread
#define ISSUE(s, k0)                                                          \
    {                                                                         \
        unsigned abase = shu + (s) * STAGE_B;                                 \
        unsigned bbase = abase + 128 * AST * 4;                               \
        _Pragma("unroll")                                                     \
        for (int j = 0; j < 4; j++) {                                         \
            int idx = t + j * 256;                                            \
            int r = idx >> 3, c4 = (idx & 7) << 2;                            \
            CPA16(abase + (unsigned)(r * AST + c4) * 4,                       \
                  A + (long)(m0 + r) * K + (k0) + c4);                        \
        }                                                                     \
        _Pragma("unroll")                                                     \
        for (int j = 0; j < 4; j++) {                                         \
            int idx = t + j * 256;                                            \
            int kk = idx >> 5, n4 = (idx & 31) << 2;                          \
            CPA16(bbase + (unsigned)(kk * BST + n4) * 4,                      \
                  Bg + (long)((k0) + kk) * N + n0 + n4);                      \
        }                                                                     \
        asm volatile("cp.async.commit_group;");                               \
    }

    const int niter = K >> 5;   // K/32
    ISSUE(0, 0);

    for (int it = 0; it < niter; it++) {
        if (it + 1 < niter) {
            ISSUE((it + 1) & 1, (it + 1) << 5);
            asm volatile("cp.async.wait_group 1;");
        } else {
            asm volatile("cp.async.wait_group 0;");
        }
        __syncthreads();

        const float* as = sh + (it & 1) * STAGE_F;
        const float* bs = as + 128 * AST;

#pragma unroll
        for (int kk = 0; kk < 32; kk += 8) {
            unsigned af[4][4], bf[4][2];
#pragma unroll
            for (int mt = 0; mt < 4; mt++) {
                int base = (wm + mt * 16 + (lane >> 2)) * AST + kk + (lane & 3);
                af[mt][0] = f2tf(as[base]);
                af[mt][1] = f2tf(as[base + 8 * AST]);
                af[mt][2] = f2tf(as[base + 4]);
                af[mt][3] = f2tf(as[base + 8 * AST + 4]);
            }
#pragma unroll
            for (int nt = 0; nt < 4; nt++) {
                int base = (kk + (lane & 3)) * BST + wn + nt * 8 + (lane >> 2);
                bf[nt][0] = f2tf(bs[base]);
                bf[nt][1] = f2tf(bs[base + 4 * BST]);
            }
#pragma unroll
            for (int mt = 0; mt < 4; mt++)
#pragma unroll
                for (int nt = 0; nt < 4; nt++) {
                    asm volatile(
                        "mma.sync.aligned.m16n8k8.row.col.f32.tf32.tf32.f32 "
                        "{%0,%1,%2,%3}, {%4,%5,%6,%7}, {%8,%9}, {%0,%1,%2,%3};"
                        : "+f"(acc[mt][nt][0]), "+f"(acc[mt][nt][1]),
                          "+f"(acc[mt][nt][2]), "+f"(acc[mt][nt][3])
                        : "r"(af[mt][0]), "r"(af[mt][1]),
                          "r"(af[mt][2]), "r"(af[mt][3]),
                          "r"(bf[nt][0]), "r"(bf[nt][1]));
                }
        }
        __syncthreads();
    }

    // ---- epilogue ---------------------------------------------------------
#pragma unroll
    for (int nt = 0; nt < 4; nt++) {
        int col = n0 + wn + nt * 8 + 2 * (lane & 3);
        float bb0 = bias ? bias[col]     : 0.f;
        float bb1 = bias ? bias[col + 1] : 0.f;
#pragma unroll
        for (int mt = 0; mt < 4; mt++) {
            int row = m0 + wm + mt * 16 + (lane >> 2);
            float2 r0, r1;
            r0.x = acc[mt][nt][0] + bb0; r0.y = acc[mt][nt][1] + bb1;
            r1.x = acc[mt][nt][2] + bb0; r1.y = acc[mt][nt][3] + bb1;
            *(float2*)&C[(long)row * N + col]       = r0;
            *(float2*)&C[(long)(row + 8) * N + col] = r1;
        }
    }
}

// ---------------------------------------------------------------------------
// RMSNorm per head (+ RoPE for Q). One warp per (row, head).
// ---------------------------------------------------------------------------
__global__ __launch_bounds__(256) void rmsnorm_rope_q(
    float* __restrict__ q, const float* __restrict__ cs,
    const float* __restrict__ sn, const float* __restrict__ w)
{
    int gw   = (blockIdx.x * blockDim.x + threadIdx.x) >> 5;
    int lane = threadIdx.x & 31;
    int row  = gw >> 4;
    int h    = gw & 15;

    float* p = q + (long)row * DIMC + h * HDIM;
    float v0 = p[lane], v1 = p[lane + 32];
    float ss = v0 * v0 + v1 * v1;
#pragma unroll
    for (int o = 16; o; o >>= 1) ss += __shfl_xor_sync(0xffffffffu, ss, o);
    float inv = rsqrtf(ss * (1.f / 64.f) + 1e-6f);

    float q0 = v0 * inv * w[lane];
    float q1 = v1 * inv * w[lane + 32];

    int n = row & (NQ - 1);
    float c0 = cs[n * HDIM + lane],      s0 = sn[n * HDIM + lane];
    float c1 = cs[n * HDIM + lane + 32], s1 = sn[n * HDIM + lane + 32];
    p[lane]      = q0 * c0 - q1 * s0;
    p[lane + 32] = q1 * c1 + q0 * s1;
}

__global__ __launch_bounds__(256) void rmsnorm_k(
    float* __restrict__ k, const float* __restrict__ w)
{
    int gw   = (blockIdx.x * blockDim.x + threadIdx.x) >> 5;
    int lane = threadIdx.x & 31;
    int row  = gw >> 4;
    int h    = gw & 15;

    float* p = k + (long)row * DIMC + h * HDIM;
    float v0 = p[lane], v1 = p[lane + 32];
    float ss = v0 * v0 + v1 * v1;
#pragma unroll
    for (int o = 16; o; o >>= 1) ss += __shfl_xor_sync(0xffffffffu, ss, o);
    float inv = rsqrtf(ss * (1.f / 64.f) + 1e-6f);
    p[lane]      = v0 * inv * w[lane];
    p[lane + 32] = v1 * inv * w[lane + 32];
}

// ---------------------------------------------------------------------------
// Attention (fp32): block = 64 queries x 1 head x 1 batch. Nc=256 keys.
// ---------------------------------------------------------------------------
#define SM_QS 0
#define SM_KT (64 * 64)
#define SM_VS (SM_KT + 64 * 257)
#define SM_S  (SM_VS + 256 * 64)
#define SM_FLOATS (SM_S + 64 * 256)

__global__ __launch_bounds__(256) void attn_kernel(
    const float* __restrict__ q, const float* __restrict__ k,
    const float* __restrict__ v, float* __restrict__ ao)
{
    extern __shared__ float sm[];
    float* Qs = sm + SM_QS;
    float* Kt = sm + SM_KT;
    float* Vs = sm + SM_VS;
    float* S  = sm + SM_S;

    const int t  = threadIdx.x;
    const int nt = blockIdx.x, h = blockIdx.y, b = blockIdx.z;
    const int qrow0  = b * NQ + nt * 64;
    const int kvrow0 = b * NCTX;
    const int cbase  = h * HDIM;

    for (int i4 = t; i4 < 64 * 16; i4 += 256) {
        int i = i4 >> 4, d4 = (i4 & 15) << 2;
        *(float4*)&Qs[i * 64 + d4] =
            *(const float4*)&q[(long)(qrow0 + i) * DIMC + cbase + d4];
    }
    for (int idx = t; idx < 256 * 64; idx += 256) {
        int j = idx >> 6, d = idx & 63;
        Kt[d * 257 + j] = k[(long)(kvrow0 + j) * DIMC + cbase + d];
    }
    for (int i4 = t; i4 < 256 * 16; i4 += 256) {
        int j = i4 >> 4, d4 = (i4 & 15) << 2;
        *(float4*)&Vs[j * 64 + d4] =
            *(const float4*)&v[(long)(kvrow0 + j) * DIMC + cbase + d4];
    }
    __syncthreads();

    const int tx = t & 31, ty = t >> 5;

    float acc[8][8];
#pragma unroll
    for (int m = 0; m < 8; m++)
#pragma unroll
        for (int n = 0; n < 8; n++) acc[m][n] = 0.f;

    for (int d = 0; d < 64; d++) {
        float ra[8], rb[8];
#pragma unroll
        for (int m = 0; m < 8; m++) ra[m] = Qs[(ty + 8 * m) * 64 + d];
#pragma unroll
        for (int n = 0; n < 8; n++) rb[n] = Kt[d * 257 + tx + 32 * n];
#pragma unroll
        for (int m = 0; m < 8; m++)
#pragma unroll
            for (int n = 0; n < 8; n++) acc[m][n] += ra[m] * rb[n];
    }
    const float scale = 0.125f;
#pragma unroll
    for (int m = 0; m < 8; m++)
#pragma unroll
        for (int n = 0; n < 8; n++)
            S[(ty + 8 * m) * 256 + tx + 32 * n] = acc[m][n] * scale;
    __syncwarp();

    for (int r = 0; r < 8; r++) {
        int i = ty + 8 * r;
        float xs[8];
        float mx = -1e30f;
#pragma unroll
        for (int n = 0; n < 8; n++) {
            xs[n] = S[i * 256 + tx + 32 * n];
            mx = fmaxf(mx, xs[n]);
        }
#pragma unroll
        for (int o = 16; o; o >>= 1)
            mx = fmaxf(mx, __shfl_xor_sync(0xffffffffu, mx, o));
        float sum = 0.f;
#pragma unroll
        for (int n = 0; n < 8; n++) { xs[n] = __expf(xs[n] - mx); sum += xs[n]; }
#pragma unroll
        for (int o = 16; o; o >>= 1) sum += __shfl_xor_sync(0xffffffffu, sum, o);
        float invs = 1.f / sum;
#pragma unroll
        for (int n = 0; n < 8; n++) S[i * 256 + tx + 32 * n] = xs[n] * invs;
    }
    __syncwarp();

    float o0[8], o1[8];
#pragma unroll
    for (int m = 0; m < 8; m++) { o0[m] = 0.f; o1[m] = 0.f; }
    for (int j = 0; j < 256; j++) {
        float va = Vs[j * 64 + tx];
        float vb = Vs[j * 64 + tx + 32];
#pragma unroll
        for (int m = 0; m < 8; m++) {
            float p = S[(ty + 8 * m) * 256 + j];
            o0[m] += p * va;
            o1[m] += p * vb;
        }
    }
#pragma unroll
    for (int m = 0; m < 8; m++) {
        long row = qrow0 + ty + 8 * m;
        ao[row * DIMC + cbase + tx]      = o0[m];
        ao[row * DIMC + cbase + tx + 32] = o1[m];
    }
}

// ---------------------------------------------------------------------------
extern "C" void kernel_launch(void* const* d_in, const int* in_sizes, int n_in,
                              void* d_out, int out_size)
{
    const float* x  = (const float*)d_in[0];
    const float* c  = (const float*)d_in[1];
    const float* rc = (const float*)d_in[2];
    const float* rs = (const float*)d_in[3];
    const float* Wq = (const float*)d_in[4];
    const float* Wk = (const float*)d_in[5];
    const float* Wv = (const float*)d_in[6];
    const float* Wo = (const float*)d_in[7];
    const float* bo = (const float*)d_in[8];
    const float* qw = (const float*)d_in[9];
    const float* kw = (const float*)d_in[10];
    float* out = (float*)d_out;

    float *q, *k, *v, *ao;
    cudaGetSymbolAddress((void**)&q,  g_q);
    cudaGetSymbolAddress((void**)&k,  g_k);
    cudaGetSymbolAddress((void**)&v,  g_v);
    cudaGetSymbolAddress((void**)&ao, g_ao);

    cudaFuncSetAttribute(gemm_tf32, cudaFuncAttributeMaxDynamicSharedMemorySize,
                         GEMM_SMEM);
    cudaFuncSetAttribute(attn_kernel, cudaFuncAttributeMaxDynamicSharedMemorySize,
                         SM_FLOATS * (int)sizeof(float));

    // Q projection: [16384,1024] @ [1024,1024]
    gemm_tf32<<<dim3(8, 128, 1), 256, GEMM_SMEM>>>(
        x, Wq, Wq, nullptr, q, q, BATCH * NQ, DIMC, DIMC);
    // K and V projections fused into one launch via blockIdx.z
    gemm_tf32<<<dim3(8, 8, 2), 256, GEMM_SMEM>>>(
        c, Wk, Wv, nullptr, k, v, BATCH * NCTX, DIMC, DIMC);

    // Norm (+RoPE on Q)
    rmsnorm_rope_q<<<(BATCH * NQ * NHEADS) / 8, 256>>>(q, rc, rs, qw);
    rmsnorm_k<<<(BATCH * NCTX * NHEADS) / 8, 256>>>(k, kw);

    // Attention (fp32)
    attn_kernel<<<dim3(NQ / 64, NHEADS, BATCH), 256,
                  SM_FLOATS * (int)sizeof(float)>>>(q, k, v, ao);

    // Output projection + bias
    gemm_tf32<<<dim3(8, 128, 1), 256, GEMM_SMEM>>>(
        ao, Wo, Wo, bo, out, out, BATCH * NQ, DIMC, DIMC);
}

// round 10
// speedup vs baseline: 1.0017x; 1.0017x over previous
#include <cuda_runtime.h>
#include <math.h>

#define DIMC   1024
#define NHEADS 16
#define HDIM   64
#define BATCH  4
#define NQ     4096
#define NCTX   256

// Scratch (no allocations allowed) ------------------------------------------
__device__ float g_q [BATCH * NQ   * DIMC];  // 64 MB
__device__ float g_k [BATCH * NCTX * DIMC];  //  4 MB
__device__ float g_v [BATCH * NCTX * DIMC];  //  4 MB
__device__ float g_ao[BATCH * NQ   * DIMC];  // 64 MB

// ===========================================================================
// tf32 tensor-core GEMM: C[M,N] = A[M,K] @ B[K,N] (+bias)
// 128x128x32 CTA tile, 256 threads (2x4 warps, warp tile 64x32),
// mma.sync.aligned.m16n8k8.row.col.f32.tf32.tf32.f32, fp32 accumulate.
// smem: A [128][36] (rows 144B, 16B-aligned; frag reads conflict-free),
//       B [32][132] (rows 528B, 16B-aligned; frag reads <=2-way).
// Double-buffered cp.async.cg 16B pipeline.
// blockIdx.z selects (B0,C0) vs (B1,C1) so K and V proj share one launch.
// ===========================================================================
#define AST 36
#define BST 132
#define STAGE_F (128 * AST + 32 * BST)   // floats per stage = 8832
#define STAGE_B (STAGE_F * 4)            // 35328 bytes
#define GEMM_SMEM (2 * STAGE_B)          // 70656 bytes

__device__ __forceinline__ unsigned f2tf(float f) {
    unsigned r;
    asm("cvt.rna.tf32.f32 %0, %1;" : "=r"(r) : "f"(f));
    return r;
}

#define CPA16(saddr, gptr) \
    asm volatile("cp.async.cg.shared.global [%0], [%1], 16;" :: "r"(saddr), "l"(gptr))

__global__ __launch_bounds__(256) void gemm_tf32(
    const float* __restrict__ A,
    const float* __restrict__ B0, const float* __restrict__ B1,
    const float* __restrict__ bias,
    float* __restrict__ C0, float* __restrict__ C1,
    int M, int N, int K)
{
    extern __shared__ float sh[];
    const float* Bg = (blockIdx.z == 0) ? B0 : B1;
    float*       C  = (blockIdx.z == 0) ? C0 : C1;

    const int t    = threadIdx.x;
    const int lane = t & 31;
    const int w    = t >> 5;
    const int wm   = (w & 1) * 64;
    const int wn   = (w >> 1) * 32;
    const int m0   = blockIdx.y * 128;
    const int n0   = blockIdx.x * 128;

    const unsigned shu = (unsigned)__cvta_generic_to_shared(sh);

    float acc[4][4][4];
#pragma unroll
    for (int mt = 0; mt < 4; mt++)
#pragma unroll
        for (int nt = 0; nt < 4; nt++)
#pragma unroll
            for (int i = 0; i < 4; i++) acc[mt][nt][i] = 0.f;

    // ---- async load of one stage -----------------------------------------
    // A tile: 128 rows x 32 cols -> 1024 float4, 4 per thread
    // B tile:  32 rows x 128 cols -> 1024 float4, 4 per thread
#define ISSUE(s, k0)                                                          \
    {                                                                         \
        unsigned abase = shu + (s) * STAGE_B;                                 \
        unsigned bbase = abase + 128 * AST * 4;                               \
        _Pragma("unroll")                                                     \
        for (int j = 0; j < 4; j++) {                                         \
            int idx = t + j * 256;                                            \
            int r = idx >> 3, c4 = (idx & 7) << 2;                            \
            CPA16(abase + (unsigned)(r * AST + c4) * 4,                       \
                  A + (long)(m0 + r) * K + (k0) + c4);                        \
        }                                                                     \
        _Pragma("unroll")                                                     \
        for (int j = 0; j < 4; j++) {                                         \
            int idx = t + j * 256;                                            \
            int kk = idx >> 5, n4 = (idx & 31) << 2;                          \
            CPA16(bbase + (unsigned)(kk * BST + n4) * 4,                      \
                  Bg + (long)((k0) + kk) * N + n0 + n4);                      \
        }                                                                     \
        asm volatile("cp.async.commit_group;");                               \
    }

    const int niter = K >> 5;   // K/32
    ISSUE(0, 0);

    for (int it = 0; it < niter; it++) {
        if (it + 1 < niter) {
            ISSUE((it + 1) & 1, (it + 1) << 5);
            asm volatile("cp.async.wait_group 1;");
        } else {
            asm volatile("cp.async.wait_group 0;");
        }
        __syncthreads();

        const float* as = sh + (it & 1) * STAGE_F;
        const float* bs = as + 128 * AST;

#pragma unroll
        for (int kk = 0; kk < 32; kk += 8) {
            unsigned af[4][4], bf[4][2];
#pragma unroll
            for (int mt = 0; mt < 4; mt++) {
                int base = (wm + mt * 16 + (lane >> 2)) * AST + kk + (lane & 3);
                af[mt][0] = f2tf(as[base]);
                af[mt][1] = f2tf(as[base + 8 * AST]);
                af[mt][2] = f2tf(as[base + 4]);
                af[mt][3] = f2tf(as[base + 8 * AST + 4]);
            }
#pragma unroll
            for (int nt = 0; nt < 4; nt++) {
                int base = (kk + (lane & 3)) * BST + wn + nt * 8 + (lane >> 2);
                bf[nt][0] = f2tf(bs[base]);
                bf[nt][1] = f2tf(bs[base + 4 * BST]);
            }
#pragma unroll
            for (int mt = 0; mt < 4; mt++)
#pragma unroll
                for (int nt = 0; nt < 4; nt++) {
                    asm volatile(
                        "mma.sync.aligned.m16n8k8.row.col.f32.tf32.tf32.f32 "
                        "{%0,%1,%2,%3}, {%4,%5,%6,%7}, {%8,%9}, {%0,%1,%2,%3};"
                        : "+f"(acc[mt][nt][0]), "+f"(acc[mt][nt][1]),
                          "+f"(acc[mt][nt][2]), "+f"(acc[mt][nt][3])
                        : "r"(af[mt][0]), "r"(af[mt][1]),
                          "r"(af[mt][2]), "r"(af[mt][3]),
                          "r"(bf[nt][0]), "r"(bf[nt][1]));
                }
        }
        __syncthreads();
    }

    // ---- epilogue ---------------------------------------------------------
#pragma unroll
    for (int nt = 0; nt < 4; nt++) {
        int col = n0 + wn + nt * 8 + 2 * (lane & 3);
        float bb0 = bias ? bias[col]     : 0.f;
        float bb1 = bias ? bias[col + 1] : 0.f;
#pragma unroll
        for (int mt = 0; mt < 4; mt++) {
            int row = m0 + wm + mt * 16 + (lane >> 2);
            float2 r0, r1;
            r0.x = acc[mt][nt][0] + bb0; r0.y = acc[mt][nt][1] + bb1;
            r1.x = acc[mt][nt][2] + bb0; r1.y = acc[mt][nt][3] + bb1;
            *(float2*)&C[(long)row * N + col]       = r0;
            *(float2*)&C[(long)(row + 8) * N + col] = r1;
        }
    }
}

// ---------------------------------------------------------------------------
// RMSNorm per head (+ RoPE for Q). One warp per (row, head).
// ---------------------------------------------------------------------------
__global__ __launch_bounds__(256) void rmsnorm_rope_q(
    float* __restrict__ q, const float* __restrict__ cs,
    const float* __restrict__ sn, const float* __restrict__ w)
{
    int gw   = (blockIdx.x * blockDim.x + threadIdx.x) >> 5;
    int lane = threadIdx.x & 31;
    int row  = gw >> 4;
    int h    = gw & 15;

    float* p = q + (long)row * DIMC + h * HDIM;
    float v0 = p[lane], v1 = p[lane + 32];
    float ss = v0 * v0 + v1 * v1;
#pragma unroll
    for (int o = 16; o; o >>= 1) ss += __shfl_xor_sync(0xffffffffu, ss, o);
    float inv = rsqrtf(ss * (1.f / 64.f) + 1e-6f);

    float q0 = v0 * inv * w[lane];
    float q1 = v1 * inv * w[lane + 32];

    int n = row & (NQ - 1);
    float c0 = cs[n * HDIM + lane],      s0 = sn[n * HDIM + lane];
    float c1 = cs[n * HDIM + lane + 32], s1 = sn[n * HDIM + lane + 32];
    p[lane]      = q0 * c0 - q1 * s0;
    p[lane + 32] = q1 * c1 + q0 * s1;
}

__global__ __launch_bounds__(256) void rmsnorm_k(
    float* __restrict__ k, const float* __restrict__ w)
{
    int gw   = (blockIdx.x * blockDim.x + threadIdx.x) >> 5;
    int lane = threadIdx.x & 31;
    int row  = gw >> 4;
    int h    = gw & 15;

    float* p = k + (long)row * DIMC + h * HDIM;
    float v0 = p[lane], v1 = p[lane + 32];
    float ss = v0 * v0 + v1 * v1;
#pragma unroll
    for (int o = 16; o; o >>= 1) ss += __shfl_xor_sync(0xffffffffu, ss, o);
    float inv = rsqrtf(ss * (1.f / 64.f) + 1e-6f);
    p[lane]      = v0 * inv * w[lane];
    p[lane + 32] = v1 * inv * w[lane + 32];
}

// ---------------------------------------------------------------------------
// Attention (fp32): block = 64 queries x 1 head x 1 batch. Nc=256 keys.
// ---------------------------------------------------------------------------
#define SM_QS 0
#define SM_KT (64 * 64)
#define SM_VS (SM_KT + 64 * 257)
#define SM_S  (SM_VS + 256 * 64)
#define SM_FLOATS (SM_S + 64 * 256)

__global__ __launch_bounds__(256) void attn_kernel(
    const float* __restrict__ q, const float* __restrict__ k,
    const float* __restrict__ v, float* __restrict__ ao)
{
    extern __shared__ float sm[];
    float* Qs = sm + SM_QS;
    float* Kt = sm + SM_KT;
    float* Vs = sm + SM_VS;
    float* S  = sm + SM_S;

    const int t  = threadIdx.x;
    const int nt = blockIdx.x, h = blockIdx.y, b = blockIdx.z;
    const int qrow0  = b * NQ + nt * 64;
    const int kvrow0 = b * NCTX;
    const int cbase  = h * HDIM;

    for (int i4 = t; i4 < 64 * 16; i4 += 256) {
        int i = i4 >> 4, d4 = (i4 & 15) << 2;
        *(float4*)&Qs[i * 64 + d4] =
            *(const float4*)&q[(long)(qrow0 + i) * DIMC + cbase + d4];
    }
    for (int idx = t; idx < 256 * 64; idx += 256) {
        int j = idx >> 6, d = idx & 63;
        Kt[d * 257 + j] = k[(long)(kvrow0 + j) * DIMC + cbase + d];
    }
    for (int i4 = t; i4 < 256 * 16; i4 += 256) {
        int j = i4 >> 4, d4 = (i4 & 15) << 2;
        *(float4*)&Vs[j * 64 + d4] =
            *(const float4*)&v[(long)(kvrow0 + j) * DIMC + cbase + d4];
    }
    __syncthreads();

    const int tx = t & 31, ty = t >> 5;

    float acc[8][8];
#pragma unroll
    for (int m = 0; m < 8; m++)
#pragma unroll
        for (int n = 0; n < 8; n++) acc[m][n] = 0.f;

    for (int d = 0; d < 64; d++) {
        float ra[8], rb[8];
#pragma unroll
        for (int m = 0; m < 8; m++) ra[m] = Qs[(ty + 8 * m) * 64 + d];
#pragma unroll
        for (int n = 0; n < 8; n++) rb[n] = Kt[d * 257 + tx + 32 * n];
#pragma unroll
        for (int m = 0; m < 8; m++)
#pragma unroll
            for (int n = 0; n < 8; n++) acc[m][n] += ra[m] * rb[n];
    }
    const float scale = 0.125f;
#pragma unroll
    for (int m = 0; m < 8; m++)
#pragma unroll
        for (int n = 0; n < 8; n++)
            S[(ty + 8 * m) * 256 + tx + 32 * n] = acc[m][n] * scale;
    __syncwarp();

    for (int r = 0; r < 8; r++) {
        int i = ty + 8 * r;
        float xs[8];
        float mx = -1e30f;
#pragma unroll
        for (int n = 0; n < 8; n++) {
            xs[n] = S[i * 256 + tx + 32 * n];
            mx = fmaxf(mx, xs[n]);
        }
#pragma unroll
        for (int o = 16; o; o >>= 1)
            mx = fmaxf(mx, __shfl_xor_sync(0xffffffffu, mx, o));
        float sum = 0.f;
#pragma unroll
        for (int n = 0; n < 8; n++) { xs[n] = __expf(xs[n] - mx); sum += xs[n]; }
#pragma unroll
        for (int o = 16; o; o >>= 1) sum += __shfl_xor_sync(0xffffffffu, sum, o);
        float invs = 1.f / sum;
#pragma unroll
        for (int n = 0; n < 8; n++) S[i * 256 + tx + 32 * n] = xs[n] * invs;
    }
    __syncwarp();

    float o0[8], o1[8];
#pragma unroll
    for (int m = 0; m < 8; m++) { o0[m] = 0.f; o1[m] = 0.f; }
    for (int j = 0; j < 256; j++) {
        float va = Vs[j * 64 + tx];
        float vb = Vs[j * 64 + tx + 32];
#pragma unroll
        for (int m = 0; m < 8; m++) {
            float p = S[(ty + 8 * m) * 256 + j];
            o0[m] += p * va;
            o1[m] += p * vb;
        }
    }
#pragma unroll
    for (int m = 0; m < 8; m++) {
        long row = qrow0 + ty + 8 * m;
        ao[row * DIMC + cbase + tx]      = o0[m];
        ao[row * DIMC + cbase + tx + 32] = o1[m];
    }
}

// ---------------------------------------------------------------------------
extern "C" void kernel_launch(void* const* d_in, const int* in_sizes, int n_in,
                              void* d_out, int out_size)
{
    const float* x  = (const float*)d_in[0];
    const float* c  = (const float*)d_in[1];
    const float* rc = (const float*)d_in[2];
    const float* rs = (const float*)d_in[3];
    const float* Wq = (const float*)d_in[4];
    const float* Wk = (const float*)d_in[5];
    const float* Wv = (const float*)d_in[6];
    const float* Wo = (const float*)d_in[7];
    const float* bo = (const float*)d_in[8];
    const float* qw = (const float*)d_in[9];
    const float* kw = (const float*)d_in[10];
    float* out = (float*)d_out;

    float *q, *k, *v, *ao;
    cudaGetSymbolAddress((void**)&q,  g_q);
    cudaGetSymbolAddress((void**)&k,  g_k);
    cudaGetSymbolAddress((void**)&v,  g_v);
    cudaGetSymbolAddress((void**)&ao, g_ao);

    cudaFuncSetAttribute(gemm_tf32, cudaFuncAttributeMaxDynamicSharedMemorySize,
                         GEMM_SMEM);
    cudaFuncSetAttribute(attn_kernel, cudaFuncAttributeMaxDynamicSharedMemorySize,
                         SM_FLOATS * (int)sizeof(float));

    // Q projection: [16384,1024] @ [1024,1024]
    gemm_tf32<<<dim3(8, 128, 1), 256, GEMM_SMEM>>>(
        x, Wq, Wq, nullptr, q, q, BATCH * NQ, DIMC, DIMC);
    // K and V projections fused into one launch via blockIdx.z
    gemm_tf32<<<dim3(8, 8, 2), 256, GEMM_SMEM>>>(
        c, Wk, Wv, nullptr, k, v, BATCH * NCTX, DIMC, DIMC);

    // Norm (+RoPE on Q)
    rmsnorm_rope_q<<<(BATCH * NQ * NHEADS) / 8, 256>>>(q, rc, rs, qw);
    rmsnorm_k<<<(BATCH * NCTX * NHEADS) / 8, 256>>>(k, kw);

    // Attention (fp32)
    attn_kernel<<<dim3(NQ / 64, NHEADS, BATCH), 256,
                  SM_FLOATS * (int)sizeof(float)>>>(q, k, v, ao);

    // Output projection + bias
    gemm_tf32<<<dim3(8, 128, 1), 256, GEMM_SMEM>>>(
        ao, Wo, Wo, bo, out, out, BATCH * NQ, DIMC, DIMC);
}

// round 11
// speedup vs baseline: 1.0042x; 1.0024x over previous
#include <cuda_runtime.h>
#include <math.h>

#define DIMC   1024
#define NHEADS 16
#define HDIM   64
#define BATCH  4
#define NQ     4096
#define NCTX   256

// Scratch (no allocations allowed) ------------------------------------------
__device__ float g_q [BATCH * NQ   * DIMC];  // 64 MB
__device__ float g_k [BATCH * NCTX * DIMC];  //  4 MB
__device__ float g_v [BATCH * NCTX * DIMC];  //  4 MB
__device__ float g_ao[BATCH * NQ   * DIMC];  // 64 MB

// ===========================================================================
// tf32 tensor-core GEMM: C[M,N] = A[M,K] @ B[K,N] (+bias)
// 128x128x32 CTA tile, 256 threads (2x4 warps, warp tile 64x32),
// mma.sync.aligned.m16n8k8.row.col.f32.tf32.tf32.f32, fp32 accumulate.
// smem: A [128][36] (rows 144B, 16B-aligned; frag reads conflict-free),
//       B [32][132] (rows 528B, 16B-aligned; frag reads <=2-way).
// Double-buffered cp.async.cg 16B pipeline.
// blockIdx.z selects (B0,C0) vs (B1,C1) so K and V proj share one launch.
// ===========================================================================
#define AST 36
#define BST 132
#define STAGE_F (128 * AST + 32 * BST)   // floats per stage = 8832
#define STAGE_B (STAGE_F * 4)            // 35328 bytes
#define GEMM_SMEM (2 * STAGE_B)          // 70656 bytes

__device__ __forceinline__ unsigned f2tf(float f) {
    unsigned r;
    asm("cvt.rna.tf32.f32 %0, %1;" : "=r"(r) : "f"(f));
    return r;
}

#define CPA16(saddr, gptr) \
    asm volatile("cp.async.cg.shared.global [%0], [%1], 16;" :: "r"(saddr), "l"(gptr))

__global__ __launch_bounds__(256) void gemm_tf32(
    const float* __restrict__ A,
    const float* __restrict__ B0, const float* __restrict__ B1,
    const float* __restrict__ bias,
    float* __restrict__ C0, float* __restrict__ C1,
    int M, int N, int K)
{
    extern __shared__ float sh[];
    const float* Bg = (blockIdx.z == 0) ? B0 : B1;
    float*       C  = (blockIdx.z == 0) ? C0 : C1;

    const int t    = threadIdx.x;
    const int lane = t & 31;
    const int w    = t >> 5;
    const int wm   = (w & 1) * 64;
    const int wn   = (w >> 1) * 32;
    const int m0   = blockIdx.y * 128;
    const int n0   = blockIdx.x * 128;

    const unsigned shu = (unsigned)__cvta_generic_to_shared(sh);

    float acc[4][4][4];
#pragma unroll
    for (int mt = 0; mt < 4; mt++)
#pragma unroll
        for (int nt = 0; nt < 4; nt++)
#pragma unroll
            for (int i = 0; i < 4; i++) acc[mt][nt][i] = 0.f;

    // ---- async load of one stage -----------------------------------------
    // A tile: 128 rows x 32 cols -> 1024 float4, 4 per thread
    // B tile:  32 rows x 128 cols -> 1024 float4, 4 per thread
#define ISSUE(s, k0)                                                          \
    {                                                                         \
        unsigned abase = shu + (s) * STAGE_B;                                 \
        unsigned bbase = abase + 128 * AST * 4;                               \
        _Pragma("unroll")                                                     \
        for (int j = 0; j < 4; j++) {                                         \
            int idx = t + j * 256;                                            \
            int r = idx >> 3, c4 = (idx & 7) << 2;                            \
            CPA16(abase + (unsigned)(r * AST + c4) * 4,                       \
                  A + (long)(m0 + r) * K + (k0) + c4);                        \
        }                                                                     \
        _Pragma("unroll")                                                     \
        for (int j = 0; j < 4; j++) {                                         \
            int idx = t + j * 256;                                            \
            int kk = idx >> 5, n4 = (idx & 31) << 2;                          \
            CPA16(bbase + (unsigned)(kk * BST + n4) * 4,                      \
                  Bg + (long)((k0) + kk) * N + n0 + n4);                      \
        }                                                                     \
        asm volatile("cp.async.commit_group;");                               \
    }

    const int niter = K >> 5;   // K/32
    ISSUE(0, 0);

    for (int it = 0; it < niter; it++) {
        if (it + 1 < niter) {
            ISSUE((it + 1) & 1, (it + 1) << 5);
            asm volatile("cp.async.wait_group 1;");
        } else {
            asm volatile("cp.async.wait_group 0;");
        }
        __syncthreads();

        const float* as = sh + (it & 1) * STAGE_F;
        const float* bs = as + 128 * AST;

#pragma unroll
        for (int kk = 0; kk < 32; kk += 8) {
            unsigned af[4][4], bf[4][2];
#pragma unroll
            for (int mt = 0; mt < 4; mt++) {
                int base = (wm + mt * 16 + (lane >> 2)) * AST + kk + (lane & 3);
                af[mt][0] = f2tf(as[base]);
                af[mt][1] = f2tf(as[base + 8 * AST]);
                af[mt][2] = f2tf(as[base + 4]);
                af[mt][3] = f2tf(as[base + 8 * AST + 4]);
            }
#pragma unroll
            for (int nt = 0; nt < 4; nt++) {
                int base = (kk + (lane & 3)) * BST + wn + nt * 8 + (lane >> 2);
                bf[nt][0] = f2tf(bs[base]);
                bf[nt][1] = f2tf(bs[base + 4 * BST]);
            }
#pragma unroll
            for (int mt = 0; mt < 4; mt++)
#pragma unroll
                for (int nt = 0; nt < 4; nt++) {
                    asm volatile(
                        "mma.sync.aligned.m16n8k8.row.col.f32.tf32.tf32.f32 "
                        "{%0,%1,%2,%3}, {%4,%5,%6,%7}, {%8,%9}, {%0,%1,%2,%3};"
                        : "+f"(acc[mt][nt][0]), "+f"(acc[mt][nt][1]),
                          "+f"(acc[mt][nt][2]), "+f"(acc[mt][nt][3])
                        : "r"(af[mt][0]), "r"(af[mt][1]),
                          "r"(af[mt][2]), "r"(af[mt][3]),
                          "r"(bf[nt][0]), "r"(bf[nt][1]));
                }
        }
        __syncthreads();
    }

    // ---- epilogue ---------------------------------------------------------
#pragma unroll
    for (int nt = 0; nt < 4; nt++) {
        int col = n0 + wn + nt * 8 + 2 * (lane & 3);
        float bb0 = bias ? bias[col]     : 0.f;
        float bb1 = bias ? bias[col + 1] : 0.f;
#pragma unroll
        for (int mt = 0; mt < 4; mt++) {
            int row = m0 + wm + mt * 16 + (lane >> 2);
            float2 r0, r1;
            r0.x = acc[mt][nt][0] + bb0; r0.y = acc[mt][nt][1] + bb1;
            r1.x = acc[mt][nt][2] + bb0; r1.y = acc[mt][nt][3] + bb1;
            *(float2*)&C[(long)row * N + col]       = r0;
            *(float2*)&C[(long)(row + 8) * N + col] = r1;
        }
    }
}

// ---------------------------------------------------------------------------
// RMSNorm per head (+ RoPE for Q). One warp per (row, head).
// ---------------------------------------------------------------------------
__global__ __launch_bounds__(256) void rmsnorm_rope_q(
    float* __restrict__ q, const float* __restrict__ cs,
    const float* __restrict__ sn, const float* __restrict__ w)
{
    int gw   = (blockIdx.x * blockDim.x + threadIdx.x) >> 5;
    int lane = threadIdx.x & 31;
    int row  = gw >> 4;
    int h    = gw & 15;

    float* p = q + (long)row * DIMC + h * HDIM;
    float v0 = p[lane], v1 = p[lane + 32];
    float ss = v0 * v0 + v1 * v1;
#pragma unroll
    for (int o = 16; o; o >>= 1) ss += __shfl_xor_sync(0xffffffffu, ss, o);
    float inv = rsqrtf(ss * (1.f / 64.f) + 1e-6f);

    float q0 = v0 * inv * w[lane];
    float q1 = v1 * inv * w[lane + 32];

    int n = row & (NQ - 1);
    float c0 = cs[n * HDIM + lane],      s0 = sn[n * HDIM + lane];
    float c1 = cs[n * HDIM + lane + 32], s1 = sn[n * HDIM + lane + 32];
    p[lane]      = q0 * c0 - q1 * s0;
    p[lane + 32] = q1 * c1 + q0 * s1;
}

__global__ __launch_bounds__(256) void rmsnorm_k(
    float* __restrict__ k, const float* __restrict__ w)
{
    int gw   = (blockIdx.x * blockDim.x + threadIdx.x) >> 5;
    int lane = threadIdx.x & 31;
    int row  = gw >> 4;
    int h    = gw & 15;

    float* p = k + (long)row * DIMC + h * HDIM;
    float v0 = p[lane], v1 = p[lane + 32];
    float ss = v0 * v0 + v1 * v1;
#pragma unroll
    for (int o = 16; o; o >>= 1) ss += __shfl_xor_sync(0xffffffffu, ss, o);
    float inv = rsqrtf(ss * (1.f / 64.f) + 1e-6f);
    p[lane]      = v0 * inv * w[lane];
    p[lane + 32] = v1 * inv * w[lane + 32];
}

// ---------------------------------------------------------------------------
// Attention (fp32): block = 64 queries x 1 head x 1 batch. Nc=256 keys.
// ---------------------------------------------------------------------------
#define SM_QS 0
#define SM_KT (64 * 64)
#define SM_VS (SM_KT + 64 * 257)
#define SM_S  (SM_VS + 256 * 64)
#define SM_FLOATS (SM_S + 64 * 256)

__global__ __launch_bounds__(256) void attn_kernel(
    const float* __restrict__ q, const float* __restrict__ k,
    const float* __restrict__ v, float* __restrict__ ao)
{
    extern __shared__ float sm[];
    float* Qs = sm + SM_QS;
    float* Kt = sm + SM_KT;
    float* Vs = sm + SM_VS;
    float* S  = sm + SM_S;

    const int t  = threadIdx.x;
    const int nt = blockIdx.x, h = blockIdx.y, b = blockIdx.z;
    const int qrow0  = b * NQ + nt * 64;
    const int kvrow0 = b * NCTX;
    const int cbase  = h * HDIM;

    for (int i4 = t; i4 < 64 * 16; i4 += 256) {
        int i = i4 >> 4, d4 = (i4 & 15) << 2;
        *(float4*)&Qs[i * 64 + d4] =
            *(const float4*)&q[(long)(qrow0 + i) * DIMC + cbase + d4];
    }
    for (int idx = t; idx < 256 * 64; idx += 256) {
        int j = idx >> 6, d = idx & 63;
        Kt[d * 257 + j] = k[(long)(kvrow0 + j) * DIMC + cbase + d];
    }
    for (int i4 = t; i4 < 256 * 16; i4 += 256) {
        int j = i4 >> 4, d4 = (i4 & 15) << 2;
        *(float4*)&Vs[j * 64 + d4] =
            *(const float4*)&v[(long)(kvrow0 + j) * DIMC + cbase + d4];
    }
    __syncthreads();

    const int tx = t & 31, ty = t >> 5;

    float acc[8][8];
#pragma unroll
    for (int m = 0; m < 8; m++)
#pragma unroll
        for (int n = 0; n < 8; n++) acc[m][n] = 0.f;

    for (int d = 0; d < 64; d++) {
        float ra[8], rb[8];
#pragma unroll
        for (int m = 0; m < 8; m++) ra[m] = Qs[(ty + 8 * m) * 64 + d];
#pragma unroll
        for (int n = 0; n < 8; n++) rb[n] = Kt[d * 257 + tx + 32 * n];
#pragma unroll
        for (int m = 0; m < 8; m++)
#pragma unroll
            for (int n = 0; n < 8; n++) acc[m][n] += ra[m] * rb[n];
    }
    const float scale = 0.125f;
#pragma unroll
    for (int m = 0; m < 8; m++)
#pragma unroll
        for (int n = 0; n < 8; n++)
            S[(ty + 8 * m) * 256 + tx + 32 * n] = acc[m][n] * scale;
    __syncwarp();

    for (int r = 0; r < 8; r++) {
        int i = ty + 8 * r;
        float xs[8];
        float mx = -1e30f;
#pragma unroll
        for (int n = 0; n < 8; n++) {
            xs[n] = S[i * 256 + tx + 32 * n];
            mx = fmaxf(mx, xs[n]);
        }
#pragma unroll
        for (int o = 16; o; o >>= 1)
            mx = fmaxf(mx, __shfl_xor_sync(0xffffffffu, mx, o));
        float sum = 0.f;
#pragma unroll
        for (int n = 0; n < 8; n++) { xs[n] = __expf(xs[n] - mx); sum += xs[n]; }
#pragma unroll
        for (int o = 16; o; o >>= 1) sum += __shfl_xor_sync(0xffffffffu, sum, o);
        float invs = 1.f / sum;
#pragma unroll
        for (int n = 0; n < 8; n++) S[i * 256 + tx + 32 * n] = xs[n] * invs;
    }
    __syncwarp();

    float o0[8], o1[8];
#pragma unroll
    for (int m = 0; m < 8; m++) { o0[m] = 0.f; o1[m] = 0.f; }
    for (int j = 0; j < 256; j++) {
        float va = Vs[j * 64 + tx];
        float vb = Vs[j * 64 + tx + 32];
#pragma unroll
        for (int m = 0; m < 8; m++) {
            float p = S[(ty + 8 * m) * 256 + j];
            o0[m] += p * va;
            o1[m] += p * vb;
        }
    }
#pragma unroll
    for (int m = 0; m < 8; m++) {
        long row = qrow0 + ty + 8 * m;
        ao[row * DIMC + cbase + tx]      = o0[m];
        ao[row * DIMC + cbase + tx + 32] = o1[m];
    }
}

// ---------------------------------------------------------------------------
extern "C" void kernel_launch(void* const* d_in, const int* in_sizes, int n_in,
                              void* d_out, int out_size)
{
    const float* x  = (const float*)d_in[0];
    const float* c  = (const float*)d_in[1];
    const float* rc = (const float*)d_in[2];
    const float* rs = (const float*)d_in[3];
    const float* Wq = (const float*)d_in[4];
    const float* Wk = (const float*)d_in[5];
    const float* Wv = (const float*)d_in[6];
    const float* Wo = (const float*)d_in[7];
    const float* bo = (const float*)d_in[8];
    const float* qw = (const float*)d_in[9];
    const float* kw = (const float*)d_in[10];
    float* out = (float*)d_out;

    float *q, *k, *v, *ao;
    cudaGetSymbolAddress((void**)&q,  g_q);
    cudaGetSymbolAddress((void**)&k,  g_k);
    cudaGetSymbolAddress((void**)&v,  g_v);
    cudaGetSymbolAddress((void**)&ao, g_ao);

    cudaFuncSetAttribute(gemm_tf32, cudaFuncAttributeMaxDynamicSharedMemorySize,
                         GEMM_SMEM);
    cudaFuncSetAttribute(attn_kernel, cudaFuncAttributeMaxDynamicSharedMemorySize,
                         SM_FLOATS * (int)sizeof(float));

    // Q projection: [16384,1024] @ [1024,1024]
    gemm_tf32<<<dim3(8, 128, 1), 256, GEMM_SMEM>>>(
        x, Wq, Wq, nullptr, q, q, BATCH * NQ, DIMC, DIMC);
    // K and V projections fused into one launch via blockIdx.z
    gemm_tf32<<<dim3(8, 8, 2), 256, GEMM_SMEM>>>(
        c, Wk, Wv, nullptr, k, v, BATCH * NCTX, DIMC, DIMC);

    // Norm (+RoPE on Q)
    rmsnorm_rope_q<<<(BATCH * NQ * NHEADS) / 8, 256>>>(q, rc, rs, qw);
    rmsnorm_k<<<(BATCH * NCTX * NHEADS) / 8, 256>>>(k, kw);

    // Attention (fp32)
    attn_kernel<<<dim3(NQ / 64, NHEADS, BATCH), 256,
                  SM_FLOATS * (int)sizeof(float)>>>(q, k, v, ao);

    // Output projection + bias
    gemm_tf32<<<dim3(8, 128, 1), 256, GEMM_SMEM>>>(
        ao, Wo, Wo, bo, out, out, BATCH * NQ, DIMC, DIMC);
}

// round 12
// speedup vs baseline: 1.2765x; 1.2712x over previous
#include <cuda_runtime.h>
#include <math.h>

#define DIMC   1024
#define NHEADS 16
#define HDIM   64
#define BATCH  4
#define NQ     4096
#define NCTX   256

// Scratch (no allocations allowed) ------------------------------------------
__device__ float g_q [BATCH * NQ   * DIMC];   // 64 MB
__device__ float g_k [BATCH * NCTX * DIMC];   //  4 MB
__device__ float g_v [BATCH * NCTX * DIMC];   //  4 MB
__device__ float g_ao[BATCH * NQ   * DIMC];   // 64 MB
__device__ float g_xr[BATCH * NQ   * DIMC];   // 64 MB  (x pre-rounded to tf32)
__device__ float g_cr[BATCH * NCTX * DIMC];   //  4 MB  (c pre-rounded)
__device__ float g_wr[4][DIMC * DIMC];        // 16 MB  (Wq,Wk,Wv,Wo pre-rounded)

__device__ __forceinline__ float tf32f(float f) {
    unsigned r;
    asm("cvt.rna.tf32.f32 %0, %1;" : "=r"(r) : "f"(f));
    return __uint_as_float(r);
}

#define MMA_TF32(C, a0, a1, a2, a3, b0, b1)                                   \
    asm volatile(                                                             \
        "mma.sync.aligned.m16n8k8.row.col.f32.tf32.tf32.f32 "                 \
        "{%0,%1,%2,%3}, {%4,%5,%6,%7}, {%8,%9}, {%0,%1,%2,%3};"               \
        : "+f"((C)[0]), "+f"((C)[1]), "+f"((C)[2]), "+f"((C)[3])              \
        : "r"(a0), "r"(a1), "r"(a2), "r"(a3), "r"(b0), "r"(b1))

// ===========================================================================
// Prep: round fp32 buffers to tf32 once (removes cvt from GEMM mainloops)
// ===========================================================================
__global__ __launch_bounds__(256) void round_tf32(
    const float* __restrict__ s, float* __restrict__ d, int n4)
{
    int i = blockIdx.x * blockDim.x + threadIdx.x;
    if (i < n4) {
        float4 v = ((const float4*)s)[i];
        v.x = tf32f(v.x); v.y = tf32f(v.y);
        v.z = tf32f(v.z); v.w = tf32f(v.w);
        ((float4*)d)[i] = v;
    }
}

__global__ __launch_bounds__(256) void round_tf32_w(
    const float* __restrict__ s0, const float* __restrict__ s1,
    const float* __restrict__ s2, const float* __restrict__ s3,
    float* __restrict__ d)
{
    const float* s = (blockIdx.y == 0) ? s0 : (blockIdx.y == 1) ? s1
                   : (blockIdx.y == 2) ? s2 : s3;
    float* dd = d + (long)blockIdx.y * (DIMC * DIMC);
    int i = blockIdx.x * blockDim.x + threadIdx.x;   // n4 = DIMC*DIMC/4 exact
    float4 v = ((const float4*)s)[i];
    v.x = tf32f(v.x); v.y = tf32f(v.y);
    v.z = tf32f(v.z); v.w = tf32f(v.w);
    ((float4*)dd)[i] = v;
}

// ===========================================================================
// tf32 tensor-core GEMM (operands pre-rounded; no cvt in mainloop)
// 128x128x32 CTA tile, 256 threads (2x4 warps, warp tile 64x32).
// ===========================================================================
#define AST 36
#define BST 132
#define STAGE_F (128 * AST + 32 * BST)
#define STAGE_B (STAGE_F * 4)
#define GEMM_SMEM (2 * STAGE_B)

#define CPA16(saddr, gptr) \
    asm volatile("cp.async.cg.shared.global [%0], [%1], 16;" :: "r"(saddr), "l"(gptr))

__global__ __launch_bounds__(256) void gemm_tf32(
    const float* __restrict__ A,
    const float* __restrict__ B0, const float* __restrict__ B1,
    const float* __restrict__ bias,
    float* __restrict__ C0, float* __restrict__ C1,
    int M, int N, int K)
{
    extern __shared__ float sh[];
    const float* Bg = (blockIdx.z == 0) ? B0 : B1;
    float*       C  = (blockIdx.z == 0) ? C0 : C1;

    const int t    = threadIdx.x;
    const int lane = t & 31;
    const int w    = t >> 5;
    const int wm   = (w & 1) * 64;
    const int wn   = (w >> 1) * 32;
    const int m0   = blockIdx.y * 128;
    const int n0   = blockIdx.x * 128;

    const unsigned shu = (unsigned)__cvta_generic_to_shared(sh);

    float acc[4][4][4];
#pragma unroll
    for (int mt = 0; mt < 4; mt++)
#pragma unroll
        for (int nt = 0; nt < 4; nt++)
#pragma unroll
            for (int i = 0; i < 4; i++) acc[mt][nt][i] = 0.f;

#define ISSUE(s, k0)                                                          \
    {                                                                         \
        unsigned abase = shu + (s) * STAGE_B;                                 \
        unsigned bbase = abase + 128 * AST * 4;                               \
        _Pragma("unroll")                                                     \
        for (int j = 0; j < 4; j++) {                                         \
            int idx = t + j * 256;                                            \
            int r = idx >> 3, c4 = (idx & 7) << 2;                            \
            CPA16(abase + (unsigned)(r * AST + c4) * 4,                       \
                  A + (long)(m0 + r) * K + (k0) + c4);                        \
        }                                                                     \
        _Pragma("unroll")                                                     \
        for (int j = 0; j < 4; j++) {                                         \
            int idx = t + j * 256;                                            \
            int kk = idx >> 5, n4 = (idx & 31) << 2;                          \
            CPA16(bbase + (unsigned)(kk * BST + n4) * 4,                      \
                  Bg + (long)((k0) + kk) * N + n0 + n4);                      \
        }                                                                     \
        asm volatile("cp.async.commit_group;");                               \
    }

    const int niter = K >> 5;
    ISSUE(0, 0);

    for (int it = 0; it < niter; it++) {
        if (it + 1 < niter) {
            ISSUE((it + 1) & 1, (it + 1) << 5);
            asm volatile("cp.async.wait_group 1;");
        } else {
            asm volatile("cp.async.wait_group 0;");
        }
        __syncthreads();

        const float* as = sh + (it & 1) * STAGE_F;
        const float* bs = as + 128 * AST;

#pragma unroll
        for (int kk = 0; kk < 32; kk += 8) {
            unsigned af[4][4], bf[4][2];
#pragma unroll
            for (int mt = 0; mt < 4; mt++) {
                int base = (wm + mt * 16 + (lane >> 2)) * AST + kk + (lane & 3);
                af[mt][0] = __float_as_uint(as[base]);
                af[mt][1] = __float_as_uint(as[base + 8 * AST]);
                af[mt][2] = __float_as_uint(as[base + 4]);
                af[mt][3] = __float_as_uint(as[base + 8 * AST + 4]);
            }
#pragma unroll
            for (int nt = 0; nt < 4; nt++) {
                int base = (kk + (lane & 3)) * BST + wn + nt * 8 + (lane >> 2);
                bf[nt][0] = __float_as_uint(bs[base]);
                bf[nt][1] = __float_as_uint(bs[base + 4 * BST]);
            }
#pragma unroll
            for (int mt = 0; mt < 4; mt++)
#pragma unroll
                for (int nt = 0; nt < 4; nt++)
                    MMA_TF32(acc[mt][nt], af[mt][0], af[mt][1], af[mt][2],
                             af[mt][3], bf[nt][0], bf[nt][1]);
        }
        __syncthreads();
    }

#pragma unroll
    for (int nt = 0; nt < 4; nt++) {
        int col = n0 + wn + nt * 8 + 2 * (lane & 3);
        float bb0 = bias ? bias[col]     : 0.f;
        float bb1 = bias ? bias[col + 1] : 0.f;
#pragma unroll
        for (int mt = 0; mt < 4; mt++) {
            int row = m0 + wm + mt * 16 + (lane >> 2);
            float2 r0, r1;
            r0.x = acc[mt][nt][0] + bb0; r0.y = acc[mt][nt][1] + bb1;
            r1.x = acc[mt][nt][2] + bb0; r1.y = acc[mt][nt][3] + bb1;
            *(float2*)&C[(long)row * N + col]       = r0;
            *(float2*)&C[(long)(row + 8) * N + col] = r1;
        }
    }
}

// ---------------------------------------------------------------------------
// RMSNorm per head (+ RoPE for Q). Outputs pre-rounded to tf32 (consumed by
// the tensor-core attention).
// ---------------------------------------------------------------------------
__global__ __launch_bounds__(256) void rmsnorm_rope_q(
    float* __restrict__ q, const float* __restrict__ cs,
    const float* __restrict__ sn, const float* __restrict__ w)
{
    int gw   = (blockIdx.x * blockDim.x + threadIdx.x) >> 5;
    int lane = threadIdx.x & 31;
    int row  = gw >> 4;
    int h    = gw & 15;

    float* p = q + (long)row * DIMC + h * HDIM;
    float v0 = p[lane], v1 = p[lane + 32];
    float ss = v0 * v0 + v1 * v1;
#pragma unroll
    for (int o = 16; o; o >>= 1) ss += __shfl_xor_sync(0xffffffffu, ss, o);
    float inv = rsqrtf(ss * (1.f / 64.f) + 1e-6f);

    float q0 = v0 * inv * w[lane];
    float q1 = v1 * inv * w[lane + 32];

    int n = row & (NQ - 1);
    float c0 = cs[n * HDIM + lane],      s0 = sn[n * HDIM + lane];
    float c1 = cs[n * HDIM + lane + 32], s1 = sn[n * HDIM + lane + 32];
    p[lane]      = tf32f(q0 * c0 - q1 * s0);
    p[lane + 32] = tf32f(q1 * c1 + q0 * s1);
}

__global__ __launch_bounds__(256) void rmsnorm_k(
    float* __restrict__ k, const float* __restrict__ w)
{
    int gw   = (blockIdx.x * blockDim.x + threadIdx.x) >> 5;
    int lane = threadIdx.x & 31;
    int row  = gw >> 4;
    int h    = gw & 15;

    float* p = k + (long)row * DIMC + h * HDIM;
    float v0 = p[lane], v1 = p[lane + 32];
    float ss = v0 * v0 + v1 * v1;
#pragma unroll
    for (int o = 16; o; o >>= 1) ss += __shfl_xor_sync(0xffffffffu, ss, o);
    float inv = rsqrtf(ss * (1.f / 64.f) + 1e-6f);
    p[lane]      = tf32f(v0 * inv * w[lane]);
    p[lane + 32] = tf32f(v1 * inv * w[lane + 32]);
}

// ===========================================================================
// Tensor-core attention: CTA = 64 queries x 1 head x 1 batch; 8 warps.
// smem (floats): Qs[64][68] | Ks[256][68] | Vt[64][260]; S[64][260] aliases
// Qs+Ks (phases separated by __syncthreads).
// QK^T: warp w -> m-tile (w&3) [16 rows], col half (w>>2) [16 n-tiles].
// PV:   warp w -> m-tile (w&3), d-quarter (w>>2) [4 n-tiles of 8].
// All fragment smem reads conflict-free via stride % 32 == 4 padding.
// ===========================================================================
#define ATT_QS 0
#define ATT_KS (64 * 68)                       // 4352
#define ATT_VT (ATT_KS + 256 * 68)             // 21760
#define ATT_FLOATS (ATT_VT + 64 * 260)         // 38400 -> 153600 B
#define ATT_S  0                               // alias over Qs+Ks

__global__ __launch_bounds__(256) void attn_mma(
    const float* __restrict__ q, const float* __restrict__ k,
    const float* __restrict__ v, float* __restrict__ ao)
{
    extern __shared__ float sm[];
    float* Qs = sm + ATT_QS;
    float* Ks = sm + ATT_KS;
    float* Vt = sm + ATT_VT;
    float* S  = sm + ATT_S;

    const int t  = threadIdx.x;
    const int nt = blockIdx.x, h = blockIdx.y, b = blockIdx.z;
    const int qrow0  = b * NQ + nt * 64;
    const int kvrow0 = b * NCTX;
    const int cbase  = h * HDIM;

    // Q tile [64][68] (already tf32-rounded by rmsnorm)
    for (int i4 = t; i4 < 64 * 16; i4 += 256) {
        int i = i4 >> 4, d4 = (i4 & 15) << 2;
        *(float4*)&Qs[i * 68 + d4] =
            *(const float4*)&q[(long)(qrow0 + i) * DIMC + cbase + d4];
    }
    // K tile [256][68]
    for (int i4 = t; i4 < 256 * 16; i4 += 256) {
        int j = i4 >> 4, d4 = (i4 & 15) << 2;
        *(float4*)&Ks[j * 68 + d4] =
            *(const float4*)&k[(long)(kvrow0 + j) * DIMC + cbase + d4];
    }
    // V transposed: Vt[d][j] = tf32(v[j][d])  (coalesced read, strided write)
    for (int idx = t; idx < 256 * 64; idx += 256) {
        int j = idx >> 6, d = idx & 63;
        Vt[d * 260 + j] = tf32f(v[(long)(kvrow0 + j) * DIMC + cbase + d]);
    }
    __syncthreads();

    const int lane = t & 31;
    const int w    = t >> 5;
    const int r0   = (w & 3) * 16;       // m-tile rows
    const int cb   = (w >> 2) * 128;     // col half for QK^T

    // ---- S = Q K^T -------------------------------------------------------
    float acc[16][4];
#pragma unroll
    for (int n = 0; n < 16; n++)
#pragma unroll
        for (int i = 0; i < 4; i++) acc[n][i] = 0.f;

#pragma unroll
    for (int ks = 0; ks < 8; ks++) {
        int d0 = ks * 8;
        int ab = (r0 + (lane >> 2)) * 68 + d0 + (lane & 3);
        unsigned a0 = __float_as_uint(Qs[ab]);
        unsigned a1 = __float_as_uint(Qs[ab + 8 * 68]);
        unsigned a2 = __float_as_uint(Qs[ab + 4]);
        unsigned a3 = __float_as_uint(Qs[ab + 8 * 68 + 4]);
#pragma unroll
        for (int n = 0; n < 16; n++) {
            int bb = (cb + n * 8 + (lane >> 2)) * 68 + d0 + (lane & 3);
            unsigned b0 = __float_as_uint(Ks[bb]);
            unsigned b1 = __float_as_uint(Ks[bb + 4]);
            MMA_TF32(acc[n], a0, a1, a2, a3, b0, b1);
        }
    }
    __syncthreads();   // all Qs/Ks reads done before S overwrites them

    const float scale = 0.125f;
#pragma unroll
    for (int n = 0; n < 16; n++) {
        int row = r0 + (lane >> 2);
        int col = cb + n * 8 + 2 * (lane & 3);
        S[row * 260 + col]           = acc[n][0] * scale;
        S[row * 260 + col + 1]       = acc[n][1] * scale;
        S[(row + 8) * 260 + col]     = acc[n][2] * scale;
        S[(row + 8) * 260 + col + 1] = acc[n][3] * scale;
    }
    __syncthreads();

    // ---- softmax: warp w owns rows {w + 8m}; P written tf32-rounded ------
    for (int r = 0; r < 8; r++) {
        int i = w + 8 * r;
        float xs[8];
        float mx = -1e30f;
#pragma unroll
        for (int n = 0; n < 8; n++) {
            xs[n] = S[i * 260 + lane + 32 * n];
            mx = fmaxf(mx, xs[n]);
        }
#pragma unroll
        for (int o = 16; o; o >>= 1)
            mx = fmaxf(mx, __shfl_xor_sync(0xffffffffu, mx, o));
        float sum = 0.f;
#pragma unroll
        for (int n = 0; n < 8; n++) { xs[n] = __expf(xs[n] - mx); sum += xs[n]; }
#pragma unroll
        for (int o = 16; o; o >>= 1) sum += __shfl_xor_sync(0xffffffffu, sum, o);
        float invs = 1.f / sum;
#pragma unroll
        for (int n = 0; n < 8; n++)
            S[i * 260 + lane + 32 * n] = tf32f(xs[n] * invs);
    }
    __syncthreads();

    // ---- O = P V ---------------------------------------------------------
    const int db = (w >> 2) * 32;        // d-quarter for PV
    float acc2[4][4];
#pragma unroll
    for (int n = 0; n < 4; n++)
#pragma unroll
        for (int i = 0; i < 4; i++) acc2[n][i] = 0.f;

#pragma unroll
    for (int ks = 0; ks < 32; ks++) {
        int j0 = ks * 8;
        int ab = (r0 + (lane >> 2)) * 260 + j0 + (lane & 3);
        unsigned a0 = __float_as_uint(S[ab]);
        unsigned a1 = __float_as_uint(S[ab + 8 * 260]);
        unsigned a2 = __float_as_uint(S[ab + 4]);
        unsigned a3 = __float_as_uint(S[ab + 8 * 260 + 4]);
#pragma unroll
        for (int n = 0; n < 4; n++) {
            int bb = (db + n * 8 + (lane >> 2)) * 260 + j0 + (lane & 3);
            unsigned b0 = __float_as_uint(Vt[bb]);
            unsigned b1 = __float_as_uint(Vt[bb + 4]);
            MMA_TF32(acc2[n], a0, a1, a2, a3, b0, b1);
        }
    }

    // store O, pre-rounded to tf32 (feeds O-projection GEMM as A operand)
#pragma unroll
    for (int n = 0; n < 4; n++) {
        long row = qrow0 + r0 + (lane >> 2);
        int  col = cbase + db + n * 8 + 2 * (lane & 3);
        ao[row * DIMC + col]           = tf32f(acc2[n][0]);
        ao[row * DIMC + col + 1]       = tf32f(acc2[n][1]);
        ao[(row + 8) * DIMC + col]     = tf32f(acc2[n][2]);
        ao[(row + 8) * DIMC + col + 1] = tf32f(acc2[n][3]);
    }
}

// ---------------------------------------------------------------------------
extern "C" void kernel_launch(void* const* d_in, const int* in_sizes, int n_in,
                              void* d_out, int out_size)
{
    const float* x  = (const float*)d_in[0];
    const float* c  = (const float*)d_in[1];
    const float* rc = (const float*)d_in[2];
    const float* rs = (const float*)d_in[3];
    const float* Wq = (const float*)d_in[4];
    const float* Wk = (const float*)d_in[5];
    const float* Wv = (const float*)d_in[6];
    const float* Wo = (const float*)d_in[7];
    const float* bo = (const float*)d_in[8];
    const float* qw = (const float*)d_in[9];
    const float* kw = (const float*)d_in[10];
    float* out = (float*)d_out;

    float *q, *k, *v, *ao, *xr, *cr, *wr;
    cudaGetSymbolAddress((void**)&q,  g_q);
    cudaGetSymbolAddress((void**)&k,  g_k);
    cudaGetSymbolAddress((void**)&v,  g_v);
    cudaGetSymbolAddress((void**)&ao, g_ao);
    cudaGetSymbolAddress((void**)&xr, g_xr);
    cudaGetSymbolAddress((void**)&cr, g_cr);
    cudaGetSymbolAddress((void**)&wr, g_wr);

    cudaFuncSetAttribute(gemm_tf32, cudaFuncAttributeMaxDynamicSharedMemorySize,
                         GEMM_SMEM);
    cudaFuncSetAttribute(attn_mma, cudaFuncAttributeMaxDynamicSharedMemorySize,
                         ATT_FLOATS * (int)sizeof(float));

    // ---- pre-round operands to tf32 --------------------------------------
    {
        int n4x = BATCH * NQ * DIMC / 4;      // 4M
        round_tf32<<<n4x / 256, 256>>>(x, xr, n4x);
        int n4c = BATCH * NCTX * DIMC / 4;    // 256K
        round_tf32<<<n4c / 256, 256>>>(c, cr, n4c);
        int n4w = DIMC * DIMC / 4;            // 256K
        round_tf32_w<<<dim3(n4w / 256, 4), 256>>>(Wq, Wk, Wv, Wo, wr);
    }
    const float* wqr = wr;
    const float* wkr = wr + (long)1 * DIMC * DIMC;
    const float* wvr = wr + (long)2 * DIMC * DIMC;
    const float* wor = wr + (long)3 * DIMC * DIMC;

    // ---- projections ------------------------------------------------------
    gemm_tf32<<<dim3(8, 128, 1), 256, GEMM_SMEM>>>(
        xr, wqr, wqr, nullptr, q, q, BATCH * NQ, DIMC, DIMC);
    gemm_tf32<<<dim3(8, 8, 2), 256, GEMM_SMEM>>>(
        cr, wkr, wvr, nullptr, k, v, BATCH * NCTX, DIMC, DIMC);

    // ---- norms (+RoPE on Q), outputs tf32-rounded -------------------------
    rmsnorm_rope_q<<<(BATCH * NQ * NHEADS) / 8, 256>>>(q, rc, rs, qw);
    rmsnorm_k<<<(BATCH * NCTX * NHEADS) / 8, 256>>>(k, kw);

    // ---- tensor-core attention -------------------------------------------
    attn_mma<<<dim3(NQ / 64, NHEADS, BATCH), 256,
               ATT_FLOATS * (int)sizeof(float)>>>(q, k, v, ao);

    // ---- output projection + bias ----------------------------------------
    gemm_tf32<<<dim3(8, 128, 1), 256, GEMM_SMEM>>>(
        ao, wor, wor, bo, out, out, BATCH * NQ, DIMC, DIMC);
}

// round 13
// speedup vs baseline: 1.3653x; 1.0695x over previous
#include <cuda_runtime.h>
#include <math.h>

#define DIMC   1024
#define NHEADS 16
#define HDIM   64
#define BATCH  4
#define NQ     4096
#define NCTX   256

// Scratch (no allocations allowed) ------------------------------------------
__device__ float g_q [BATCH * NQ   * DIMC];   // 64 MB
__device__ float g_k [BATCH * NCTX * DIMC];   //  4 MB
__device__ float g_v [BATCH * NCTX * DIMC];   //  4 MB
__device__ float g_ao[BATCH * NQ   * DIMC];   // 64 MB
__device__ float g_xr[BATCH * NQ   * DIMC];   // 64 MB  x pre-rounded tf32
__device__ float g_cr[BATCH * NCTX * DIMC];   //  4 MB  c pre-rounded
__device__ float g_wt[4][DIMC * DIMC];        // 16 MB  W^T, tf32-rounded

__device__ __forceinline__ float tf32f(float f) {
    unsigned r;
    asm("cvt.rna.tf32.f32 %0, %1;" : "=r"(r) : "f"(f));
    return __uint_as_float(r);
}

#define MMA_TF32(C, a0, a1, a2, a3, b0, b1)                                   \
    asm volatile(                                                             \
        "mma.sync.aligned.m16n8k8.row.col.f32.tf32.tf32.f32 "                 \
        "{%0,%1,%2,%3}, {%4,%5,%6,%7}, {%8,%9}, {%0,%1,%2,%3};"               \
        : "+f"((C)[0]), "+f"((C)[1]), "+f"((C)[2]), "+f"((C)[3])              \
        : "r"(a0), "r"(a1), "r"(a2), "r"(a3), "r"(b0), "r"(b1))

// ldmatrix x4: four 8-row x 16B tiles; lane L supplies the address of row
// (L&7) of matrix (L>>3). Register i <- matrix i; thread gets word lane&3 of
// row lane>>2 (exactly the tf32 mma fragment distribution).
#define LDSM4(r0, r1, r2, r3, saddr)                                          \
    asm volatile("ldmatrix.sync.aligned.m8n8.x4.shared.b16 {%0,%1,%2,%3}, [%4];" \
        : "=r"(r0), "=r"(r1), "=r"(r2), "=r"(r3) : "r"(saddr))

#define CPA16(saddr, gptr) \
    asm volatile("cp.async.cg.shared.global [%0], [%1], 16;" :: "r"(saddr), "l"(gptr))

// ===========================================================================
// Prep kernels
// ===========================================================================
__global__ __launch_bounds__(256) void round_tf32(
    const float* __restrict__ s, float* __restrict__ d, int n4)
{
    int i = blockIdx.x * blockDim.x + threadIdx.x;
    if (i < n4) {
        float4 v = ((const float4*)s)[i];
        v.x = tf32f(v.x); v.y = tf32f(v.y);
        v.z = tf32f(v.z); v.w = tf32f(v.w);
        ((float4*)d)[i] = v;
    }
}

// Transpose + tf32-round weights: Wt[n][k] = tf32(W[k][n])
__global__ __launch_bounds__(256) void trans_round_w(
    const float* __restrict__ s0, const float* __restrict__ s1,
    const float* __restrict__ s2, const float* __restrict__ s3,
    float* __restrict__ d)
{
    const float* s = (blockIdx.z == 0) ? s0 : (blockIdx.z == 1) ? s1
                   : (blockIdx.z == 2) ? s2 : s3;
    float* dd = d + (long)blockIdx.z * (DIMC * DIMC);
    __shared__ float t[32][33];
    int tx = threadIdx.x & 31, ty = threadIdx.x >> 5;   // 32 x 8
    int bx = blockIdx.x * 32, by = blockIdx.y * 32;
#pragma unroll
    for (int i = 0; i < 32; i += 8)
        t[ty + i][tx] = tf32f(s[(long)(by + ty + i) * DIMC + bx + tx]);
    __syncthreads();
#pragma unroll
    for (int i = 0; i < 32; i += 8)
        dd[(long)(bx + ty + i) * DIMC + by + tx] = t[tx][ty + i];
}

// ===========================================================================
// tf32 GEMM, B pre-transposed (k-major): C[m][n] = sum_k A[m][k]*Bt[n][k]
// 128x128x32 CTA tile, 256 threads (2x4 warps, warp tile 64x32).
// smem: As[128][36], Bs[128][36] per stage; all fragments via ldmatrix.x4.
// ===========================================================================
#define AST 36
#define STAGE_F (2 * 128 * AST)          // 9216 floats
#define STAGE_B (STAGE_F * 4)            // 36864 bytes
#define GEMM_SMEM (2 * STAGE_B)          // 73728 bytes

__global__ __launch_bounds__(256) void gemm_tf32(
    const float* __restrict__ A,
    const float* __restrict__ Bt0, const float* __restrict__ Bt1,
    const float* __restrict__ bias,
    float* __restrict__ C0, float* __restrict__ C1,
    int M, int N, int K)
{
    extern __shared__ float sh[];
    const float* Bt = (blockIdx.z == 0) ? Bt0 : Bt1;
    float*       C  = (blockIdx.z == 0) ? C0 : C1;

    const int t    = threadIdx.x;
    const int lane = t & 31;
    const int w    = t >> 5;
    const int wm   = (w & 1) * 64;
    const int wn   = (w >> 1) * 32;
    const int m0   = blockIdx.y * 128;
    const int n0   = blockIdx.x * 128;

    const unsigned shu = (unsigned)__cvta_generic_to_shared(sh);

    float acc[4][4][4];
#pragma unroll
    for (int mt = 0; mt < 4; mt++)
#pragma unroll
        for (int nt = 0; nt < 4; nt++)
#pragma unroll
            for (int i = 0; i < 4; i++) acc[mt][nt][i] = 0.f;

    // per-stage load: A 128x32, Bt 128x32 -> 2048 float4, 8 per thread
#define ISSUE(s, k0)                                                          \
    {                                                                         \
        unsigned abase = shu + (s) * STAGE_B;                                 \
        unsigned bbase = abase + 128 * AST * 4;                               \
        _Pragma("unroll")                                                     \
        for (int j = 0; j < 4; j++) {                                         \
            int idx = t + j * 256;                                            \
            int r = idx >> 3, c4 = (idx & 7) << 2;                            \
            CPA16(abase + (unsigned)(r * AST + c4) * 4,                       \
                  A + (long)(m0 + r) * K + (k0) + c4);                        \
            CPA16(bbase + (unsigned)(r * AST + c4) * 4,                       \
                  Bt + (long)(n0 + r) * K + (k0) + c4);                       \
        }                                                                     \
        asm volatile("cp.async.commit_group;");                               \
    }

    // ldmatrix lane address components (element offsets)
    const int aSel = ((lane >> 3) & 1) * 8 + (lane & 7);   // row within 16
    const int cSel = (lane >> 4) * 4;                      // col 0/4 (A)
    const int bRowSel = (lane >> 4) * 8 + (lane & 7);      // row within 16 (B)
    const int bColSel = ((lane >> 3) & 1) * 4;             // col 0/4 (B)

    const int niter = K >> 5;
    ISSUE(0, 0);

    for (int it = 0; it < niter; it++) {
        if (it + 1 < niter) {
            ISSUE((it + 1) & 1, (it + 1) << 5);
            asm volatile("cp.async.wait_group 1;");
        } else {
            asm volatile("cp.async.wait_group 0;");
        }
        __syncthreads();

        unsigned as_u = shu + (it & 1) * STAGE_B;
        unsigned bs_u = as_u + 128 * AST * 4;

#pragma unroll
        for (int kk = 0; kk < 32; kk += 8) {
            unsigned af[4][4], bf[4][2];
#pragma unroll
            for (int mt = 0; mt < 4; mt++) {
                unsigned ad = as_u +
                    (unsigned)((wm + mt * 16 + aSel) * AST + kk + cSel) * 4;
                LDSM4(af[mt][0], af[mt][1], af[mt][2], af[mt][3], ad);
            }
#pragma unroll
            for (int p = 0; p < 2; p++) {   // covers nt = 2p, 2p+1
                unsigned bd = bs_u +
                    (unsigned)((wn + p * 16 + bRowSel) * AST + kk + bColSel) * 4;
                LDSM4(bf[2 * p][0], bf[2 * p][1], bf[2 * p + 1][0],
                      bf[2 * p + 1][1], bd);
            }
#pragma unroll
            for (int mt = 0; mt < 4; mt++)
#pragma unroll
                for (int nt = 0; nt < 4; nt++)
                    MMA_TF32(acc[mt][nt], af[mt][0], af[mt][1], af[mt][2],
                             af[mt][3], bf[nt][0], bf[nt][1]);
        }
        __syncthreads();
    }

#pragma unroll
    for (int nt = 0; nt < 4; nt++) {
        int col = n0 + wn + nt * 8 + 2 * (lane & 3);
        float bb0 = bias ? bias[col]     : 0.f;
        float bb1 = bias ? bias[col + 1] : 0.f;
#pragma unroll
        for (int mt = 0; mt < 4; mt++) {
            int row = m0 + wm + mt * 16 + (lane >> 2);
            float2 r0, r1;
            r0.x = acc[mt][nt][0] + bb0; r0.y = acc[mt][nt][1] + bb1;
            r1.x = acc[mt][nt][2] + bb0; r1.y = acc[mt][nt][3] + bb1;
            *(float2*)&C[(long)row * N + col]       = r0;
            *(float2*)&C[(long)(row + 8) * N + col] = r1;
        }
    }
}

// ---------------------------------------------------------------------------
// RMSNorm per head (+ RoPE for Q). Outputs tf32-rounded.
// ---------------------------------------------------------------------------
__global__ __launch_bounds__(256) void rmsnorm_rope_q(
    float* __restrict__ q, const float* __restrict__ cs,
    const float* __restrict__ sn, const float* __restrict__ w)
{
    int gw   = (blockIdx.x * blockDim.x + threadIdx.x) >> 5;
    int lane = threadIdx.x & 31;
    int row  = gw >> 4;
    int h    = gw & 15;

    float* p = q + (long)row * DIMC + h * HDIM;
    float v0 = p[lane], v1 = p[lane + 32];
    float ss = v0 * v0 + v1 * v1;
#pragma unroll
    for (int o = 16; o; o >>= 1) ss += __shfl_xor_sync(0xffffffffu, ss, o);
    float inv = rsqrtf(ss * (1.f / 64.f) + 1e-6f);

    float q0 = v0 * inv * w[lane];
    float q1 = v1 * inv * w[lane + 32];

    int n = row & (NQ - 1);
    float c0 = cs[n * HDIM + lane],      s0 = sn[n * HDIM + lane];
    float c1 = cs[n * HDIM + lane + 32], s1 = sn[n * HDIM + lane + 32];
    p[lane]      = tf32f(q0 * c0 - q1 * s0);
    p[lane + 32] = tf32f(q1 * c1 + q0 * s1);
}

__global__ __launch_bounds__(256) void rmsnorm_k(
    float* __restrict__ k, const float* __restrict__ w)
{
    int gw   = (blockIdx.x * blockDim.x + threadIdx.x) >> 5;
    int lane = threadIdx.x & 31;
    int row  = gw >> 4;
    int h    = gw & 15;

    float* p = k + (long)row * DIMC + h * HDIM;
    float v0 = p[lane], v1 = p[lane + 32];
    float ss = v0 * v0 + v1 * v1;
#pragma unroll
    for (int o = 16; o; o >>= 1) ss += __shfl_xor_sync(0xffffffffu, ss, o);
    float inv = rsqrtf(ss * (1.f / 64.f) + 1e-6f);
    p[lane]      = tf32f(v0 * inv * w[lane]);
    p[lane + 32] = tf32f(v1 * inv * w[lane + 32]);
}

// ===========================================================================
// Tensor-core attention (ldmatrix fragments): CTA = 64 q x 1 head x 1 batch.
// smem: Qs[64][68] | Ks[256][68] | Vt[64][260]; S[64][260] aliases Qs+Ks.
// ===========================================================================
#define ATT_QS 0
#define ATT_KS (64 * 68)
#define ATT_VT (ATT_KS + 256 * 68)
#define ATT_FLOATS (ATT_VT + 64 * 260)
#define ATT_S  0

__global__ __launch_bounds__(256) void attn_mma(
    const float* __restrict__ q, const float* __restrict__ k,
    const float* __restrict__ v, float* __restrict__ ao)
{
    extern __shared__ float sm[];
    float* Qs = sm + ATT_QS;
    float* Ks = sm + ATT_KS;
    float* Vt = sm + ATT_VT;
    float* S  = sm + ATT_S;
    const unsigned shu = (unsigned)__cvta_generic_to_shared(sm);
    const unsigned qs_u = shu, ks_u = shu + ATT_KS * 4;
    const unsigned vt_u = shu + ATT_VT * 4, s_u = shu;

    const int t  = threadIdx.x;
    const int nt = blockIdx.x, h = blockIdx.y, b = blockIdx.z;
    const int qrow0  = b * NQ + nt * 64;
    const int kvrow0 = b * NCTX;
    const int cbase  = h * HDIM;

    for (int i4 = t; i4 < 64 * 16; i4 += 256) {
        int i = i4 >> 4, d4 = (i4 & 15) << 2;
        *(float4*)&Qs[i * 68 + d4] =
            *(const float4*)&q[(long)(qrow0 + i) * DIMC + cbase + d4];
    }
    for (int i4 = t; i4 < 256 * 16; i4 += 256) {
        int j = i4 >> 4, d4 = (i4 & 15) << 2;
        *(float4*)&Ks[j * 68 + d4] =
            *(const float4*)&k[(long)(kvrow0 + j) * DIMC + cbase + d4];
    }
    for (int idx = t; idx < 256 * 64; idx += 256) {
        int j = idx >> 6, d = idx & 63;
        Vt[d * 260 + j] = tf32f(v[(long)(kvrow0 + j) * DIMC + cbase + d]);
    }
    __syncthreads();

    const int lane = t & 31;
    const int w    = t >> 5;
    const int r0   = (w & 3) * 16;       // m-tile (16 q rows)
    const int cb   = (w >> 2) * 128;     // col half for QK^T

    const int aSel = ((lane >> 3) & 1) * 8 + (lane & 7);
    const int cSel = (lane >> 4) * 4;
    const int bRowSel = (lane >> 4) * 8 + (lane & 7);
    const int bColSel = ((lane >> 3) & 1) * 4;

    // ---- S = Q K^T -------------------------------------------------------
    float acc[16][4];
#pragma unroll
    for (int n = 0; n < 16; n++)
#pragma unroll
        for (int i = 0; i < 4; i++) acc[n][i] = 0.f;

#pragma unroll
    for (int ks = 0; ks < 8; ks++) {
        int d0 = ks * 8;
        unsigned a0, a1, a2, a3;
        LDSM4(a0, a1, a2, a3,
              qs_u + (unsigned)((r0 + aSel) * 68 + d0 + cSel) * 4);
#pragma unroll
        for (int p = 0; p < 8; p++) {    // covers n-tiles 2p, 2p+1
            unsigned b0, b1, b2, b3;
            LDSM4(b0, b1, b2, b3,
                  ks_u + (unsigned)((cb + p * 16 + bRowSel) * 68 + d0 + bColSel) * 4);
            MMA_TF32(acc[2 * p],     a0, a1, a2, a3, b0, b1);
            MMA_TF32(acc[2 * p + 1], a0, a1, a2, a3, b2, b3);
        }
    }
    __syncthreads();   // Qs/Ks reads complete before S overwrites

    const float scale = 0.125f;
#pragma unroll
    for (int n = 0; n < 16; n++) {
        int row = r0 + (lane >> 2);
        int col = cb + n * 8 + 2 * (lane & 3);
        S[row * 260 + col]           = acc[n][0] * scale;
        S[row * 260 + col + 1]       = acc[n][1] * scale;
        S[(row + 8) * 260 + col]     = acc[n][2] * scale;
        S[(row + 8) * 260 + col + 1] = acc[n][3] * scale;
    }
    __syncthreads();

    // ---- softmax: warp w owns rows {w + 8m}; P written tf32 --------------
    for (int r = 0; r < 8; r++) {
        int i = w + 8 * r;
        float xs[8];
        float mx = -1e30f;
#pragma unroll
        for (int n = 0; n < 8; n++) {
            xs[n] = S[i * 260 + lane + 32 * n];
            mx = fmaxf(mx, xs[n]);
        }
#pragma unroll
        for (int o = 16; o; o >>= 1)
            mx = fmaxf(mx, __shfl_xor_sync(0xffffffffu, mx, o));
        float sum = 0.f;
#pragma unroll
        for (int n = 0; n < 8; n++) { xs[n] = __expf(xs[n] - mx); sum += xs[n]; }
#pragma unroll
        for (int o = 16; o; o >>= 1) sum += __shfl_xor_sync(0xffffffffu, sum, o);
        float invs = 1.f / sum;
#pragma unroll
        for (int n = 0; n < 8; n++)
            S[i * 260 + lane + 32 * n] = tf32f(xs[n] * invs);
    }
    __syncthreads();

    // ---- O = P V ---------------------------------------------------------
    const int db = (w >> 2) * 32;        // d-quarter
    float acc2[4][4];
#pragma unroll
    for (int n = 0; n < 4; n++)
#pragma unroll
        for (int i = 0; i < 4; i++) acc2[n][i] = 0.f;

#pragma unroll
    for (int ks = 0; ks < 32; ks++) {
        int j0 = ks * 8;
        unsigned a0, a1, a2, a3;
        LDSM4(a0, a1, a2, a3,
              s_u + (unsigned)((r0 + aSel) * 260 + j0 + cSel) * 4);
#pragma unroll
        for (int p = 0; p < 2; p++) {    // covers d-tiles 2p, 2p+1
            unsigned b0, b1, b2, b3;
            LDSM4(b0, b1, b2, b3,
                  vt_u + (unsigned)((db + p * 16 + bRowSel) * 260 + j0 + bColSel) * 4);
            MMA_TF32(acc2[2 * p],     a0, a1, a2, a3, b0, b1);
            MMA_TF32(acc2[2 * p + 1], a0, a1, a2, a3, b2, b3);
        }
    }

#pragma unroll
    for (int n = 0; n < 4; n++) {
        long row = qrow0 + r0 + (lane >> 2);
        int  col = cbase + db + n * 8 + 2 * (lane & 3);
        ao[row * DIMC + col]           = tf32f(acc2[n][0]);
        ao[row * DIMC + col + 1]       = tf32f(acc2[n][1]);
        ao[(row + 8) * DIMC + col]     = tf32f(acc2[n][2]);
        ao[(row + 8) * DIMC + col + 1] = tf32f(acc2[n][3]);
    }
}

// ---------------------------------------------------------------------------
extern "C" void kernel_launch(void* const* d_in, const int* in_sizes, int n_in,
                              void* d_out, int out_size)
{
    const float* x  = (const float*)d_in[0];
    const float* c  = (const float*)d_in[1];
    const float* rc = (const float*)d_in[2];
    const float* rs = (const float*)d_in[3];
    const float* Wq = (const float*)d_in[4];
    const float* Wk = (const float*)d_in[5];
    const float* Wv = (const float*)d_in[6];
    const float* Wo = (const float*)d_in[7];
    const float* bo = (const float*)d_in[8];
    const float* qw = (const float*)d_in[9];
    const float* kw = (const float*)d_in[10];
    float* out = (float*)d_out;

    float *q, *k, *v, *ao, *xr, *cr, *wt;
    cudaGetSymbolAddress((void**)&q,  g_q);
    cudaGetSymbolAddress((void**)&k,  g_k);
    cudaGetSymbolAddress((void**)&v,  g_v);
    cudaGetSymbolAddress((void**)&ao, g_ao);
    cudaGetSymbolAddress((void**)&xr, g_xr);
    cudaGetSymbolAddress((void**)&cr, g_cr);
    cudaGetSymbolAddress((void**)&wt, g_wt);

    cudaFuncSetAttribute(gemm_tf32, cudaFuncAttributeMaxDynamicSharedMemorySize,
                         GEMM_SMEM);
    cudaFuncSetAttribute(attn_mma, cudaFuncAttributeMaxDynamicSharedMemorySize,
                         ATT_FLOATS * (int)sizeof(float));

    // ---- prep: round activations, transpose+round weights ----------------
    {
        int n4x = BATCH * NQ * DIMC / 4;
        round_tf32<<<n4x / 256, 256>>>(x, xr, n4x);
        int n4c = BATCH * NCTX * DIMC / 4;
        round_tf32<<<n4c / 256, 256>>>(c, cr, n4c);
        trans_round_w<<<dim3(32, 32, 4), 256>>>(Wq, Wk, Wv, Wo, wt);
    }
    const float* wqt = wt;
    const float* wkt = wt + (long)1 * DIMC * DIMC;
    const float* wvt = wt + (long)2 * DIMC * DIMC;
    const float* wot = wt + (long)3 * DIMC * DIMC;

    // ---- projections ------------------------------------------------------
    gemm_tf32<<<dim3(8, 128, 1), 256, GEMM_SMEM>>>(
        xr, wqt, wqt, nullptr, q, q, BATCH * NQ, DIMC, DIMC);
    gemm_tf32<<<dim3(8, 8, 2), 256, GEMM_SMEM>>>(
        cr, wkt, wvt, nullptr, k, v, BATCH * NCTX, DIMC, DIMC);

    // ---- norms (+RoPE on Q) ----------------------------------------------
    rmsnorm_rope_q<<<(BATCH * NQ * NHEADS) / 8, 256>>>(q, rc, rs, qw);
    rmsnorm_k<<<(BATCH * NCTX * NHEADS) / 8, 256>>>(k, kw);

    // ---- attention --------------------------------------------------------
    attn_mma<<<dim3(NQ / 64, NHEADS, BATCH), 256,
               ATT_FLOATS * (int)sizeof(float)>>>(q, k, v, ao);

    // ---- output projection + bias ----------------------------------------
    gemm_tf32<<<dim3(8, 128, 1), 256, GEMM_SMEM>>>(
        ao, wot, wot, bo, out, out, BATCH * NQ, DIMC, DIMC);
}

// round 14
// speedup vs baseline: 1.6754x; 1.2272x over previous
#include <cuda_runtime.h>
#include <math.h>

#define DIMC   1024
#define NHEADS 16
#define HDIM   64
#define BATCH  4
#define NQ     4096
#define NCTX   256

// Scratch (no allocations allowed) ------------------------------------------
__device__ float g_q [BATCH * NQ   * DIMC];   // 64 MB
__device__ float g_k [BATCH * NCTX * DIMC];   //  4 MB
__device__ float g_v [BATCH * NCTX * DIMC];   //  4 MB (tf32-rounded by GEMM)
__device__ float g_ao[BATCH * NQ   * DIMC];   // 64 MB
__device__ float g_xr[BATCH * NQ   * DIMC];   // 64 MB  x pre-rounded tf32
__device__ float g_cr[BATCH * NCTX * DIMC];   //  4 MB  c pre-rounded
__device__ float g_wt[4][DIMC * DIMC];        // 16 MB  W^T, tf32-rounded

__device__ __forceinline__ float tf32f(float f) {
    unsigned r;
    asm("cvt.rna.tf32.f32 %0, %1;" : "=r"(r) : "f"(f));
    return __uint_as_float(r);
}

#define MMA_TF32(C, a0, a1, a2, a3, b0, b1)                                   \
    asm volatile(                                                             \
        "mma.sync.aligned.m16n8k8.row.col.f32.tf32.tf32.f32 "                 \
        "{%0,%1,%2,%3}, {%4,%5,%6,%7}, {%8,%9}, {%0,%1,%2,%3};"               \
        : "+f"((C)[0]), "+f"((C)[1]), "+f"((C)[2]), "+f"((C)[3])              \
        : "r"(a0), "r"(a1), "r"(a2), "r"(a3), "r"(b0), "r"(b1))

#define LDSM4(r0, r1, r2, r3, saddr)                                          \
    asm volatile("ldmatrix.sync.aligned.m8n8.x4.shared.b16 {%0,%1,%2,%3}, [%4];" \
        : "=r"(r0), "=r"(r1), "=r"(r2), "=r"(r3) : "r"(saddr))

#define CPA16(saddr, gptr) \
    asm volatile("cp.async.cg.shared.global [%0], [%1], 16;" :: "r"(saddr), "l"(gptr))

// ===========================================================================
// Prep kernels
// ===========================================================================
__global__ __launch_bounds__(256) void round_tf32(
    const float* __restrict__ s, float* __restrict__ d, int n4)
{
    int i = blockIdx.x * blockDim.x + threadIdx.x;
    if (i < n4) {
        float4 v = ((const float4*)s)[i];
        v.x = tf32f(v.x); v.y = tf32f(v.y);
        v.z = tf32f(v.z); v.w = tf32f(v.w);
        ((float4*)d)[i] = v;
    }
}

__global__ __launch_bounds__(256) void trans_round_w(
    const float* __restrict__ s0, const float* __restrict__ s1,
    const float* __restrict__ s2, const float* __restrict__ s3,
    float* __restrict__ d)
{
    const float* s = (blockIdx.z == 0) ? s0 : (blockIdx.z == 1) ? s1
                   : (blockIdx.z == 2) ? s2 : s3;
    float* dd = d + (long)blockIdx.z * (DIMC * DIMC);
    __shared__ float t[32][33];
    int tx = threadIdx.x & 31, ty = threadIdx.x >> 5;
    int bx = blockIdx.x * 32, by = blockIdx.y * 32;
#pragma unroll
    for (int i = 0; i < 32; i += 8)
        t[ty + i][tx] = tf32f(s[(long)(by + ty + i) * DIMC + bx + tx]);
    __syncthreads();
#pragma unroll
    for (int i = 0; i < 32; i += 8)
        dd[(long)(bx + ty + i) * DIMC + by + tx] = t[tx][ty + i];
}

// ===========================================================================
// tf32 GEMM, B pre-transposed (k-major). 128x128x32 tile, 256 thr, ldmatrix.
// roundC != 0 -> output tf32-rounded (used for K/V feeding attention).
// ===========================================================================
#define AST 36
#define STAGE_F (2 * 128 * AST)
#define STAGE_B (STAGE_F * 4)
#define GEMM_SMEM (2 * STAGE_B)

__global__ __launch_bounds__(256) void gemm_tf32(
    const float* __restrict__ A,
    const float* __restrict__ Bt0, const float* __restrict__ Bt1,
    const float* __restrict__ bias,
    float* __restrict__ C0, float* __restrict__ C1,
    int M, int N, int K, int roundC)
{
    extern __shared__ float sh[];
    const float* Bt = (blockIdx.z == 0) ? Bt0 : Bt1;
    float*       C  = (blockIdx.z == 0) ? C0 : C1;

    const int t    = threadIdx.x;
    const int lane = t & 31;
    const int w    = t >> 5;
    const int wm   = (w & 1) * 64;
    const int wn   = (w >> 1) * 32;
    const int m0   = blockIdx.y * 128;
    const int n0   = blockIdx.x * 128;

    const unsigned shu = (unsigned)__cvta_generic_to_shared(sh);

    float acc[4][4][4];
#pragma unroll
    for (int mt = 0; mt < 4; mt++)
#pragma unroll
        for (int nt = 0; nt < 4; nt++)
#pragma unroll
            for (int i = 0; i < 4; i++) acc[mt][nt][i] = 0.f;

#define ISSUE(s, k0)                                                          \
    {                                                                         \
        unsigned abase = shu + (s) * STAGE_B;                                 \
        unsigned bbase = abase + 128 * AST * 4;                               \
        _Pragma("unroll")                                                     \
        for (int j = 0; j < 4; j++) {                                         \
            int idx = t + j * 256;                                            \
            int r = idx >> 3, c4 = (idx & 7) << 2;                            \
            CPA16(abase + (unsigned)(r * AST + c4) * 4,                       \
                  A + (long)(m0 + r) * K + (k0) + c4);                        \
            CPA16(bbase + (unsigned)(r * AST + c4) * 4,                       \
                  Bt + (long)(n0 + r) * K + (k0) + c4);                       \
        }                                                                     \
        asm volatile("cp.async.commit_group;");                               \
    }

    const int aSel = ((lane >> 3) & 1) * 8 + (lane & 7);
    const int cSel = (lane >> 4) * 4;
    const int bRowSel = (lane >> 4) * 8 + (lane & 7);
    const int bColSel = ((lane >> 3) & 1) * 4;

    const int niter = K >> 5;
    ISSUE(0, 0);

    for (int it = 0; it < niter; it++) {
        if (it + 1 < niter) {
            ISSUE((it + 1) & 1, (it + 1) << 5);
            asm volatile("cp.async.wait_group 1;");
        } else {
            asm volatile("cp.async.wait_group 0;");
        }
        __syncthreads();

        unsigned as_u = shu + (it & 1) * STAGE_B;
        unsigned bs_u = as_u + 128 * AST * 4;

#pragma unroll
        for (int kk = 0; kk < 32; kk += 8) {
            unsigned af[4][4], bf[4][2];
#pragma unroll
            for (int mt = 0; mt < 4; mt++) {
                unsigned ad = as_u +
                    (unsigned)((wm + mt * 16 + aSel) * AST + kk + cSel) * 4;
                LDSM4(af[mt][0], af[mt][1], af[mt][2], af[mt][3], ad);
            }
#pragma unroll
            for (int p = 0; p < 2; p++) {
                unsigned bd = bs_u +
                    (unsigned)((wn + p * 16 + bRowSel) * AST + kk + bColSel) * 4;
                LDSM4(bf[2 * p][0], bf[2 * p][1], bf[2 * p + 1][0],
                      bf[2 * p + 1][1], bd);
            }
#pragma unroll
            for (int mt = 0; mt < 4; mt++)
#pragma unroll
                for (int nt = 0; nt < 4; nt++)
                    MMA_TF32(acc[mt][nt], af[mt][0], af[mt][1], af[mt][2],
                             af[mt][3], bf[nt][0], bf[nt][1]);
        }
        __syncthreads();
    }

#pragma unroll
    for (int nt = 0; nt < 4; nt++) {
        int col = n0 + wn + nt * 8 + 2 * (lane & 3);
        float bb0 = bias ? bias[col]     : 0.f;
        float bb1 = bias ? bias[col + 1] : 0.f;
#pragma unroll
        for (int mt = 0; mt < 4; mt++) {
            int row = m0 + wm + mt * 16 + (lane >> 2);
            float2 r0, r1;
            r0.x = acc[mt][nt][0] + bb0; r0.y = acc[mt][nt][1] + bb1;
            r1.x = acc[mt][nt][2] + bb0; r1.y = acc[mt][nt][3] + bb1;
            if (roundC) {
                r0.x = tf32f(r0.x); r0.y = tf32f(r0.y);
                r1.x = tf32f(r1.x); r1.y = tf32f(r1.y);
            }
            *(float2*)&C[(long)row * N + col]       = r0;
            *(float2*)&C[(long)(row + 8) * N + col] = r1;
        }
    }
}

// ---------------------------------------------------------------------------
// RMSNorm per head (+ RoPE for Q). Outputs tf32-rounded.
// ---------------------------------------------------------------------------
__global__ __launch_bounds__(256) void rmsnorm_rope_q(
    float* __restrict__ q, const float* __restrict__ cs,
    const float* __restrict__ sn, const float* __restrict__ w)
{
    int gw   = (blockIdx.x * blockDim.x + threadIdx.x) >> 5;
    int lane = threadIdx.x & 31;
    int row  = gw >> 4;
    int h    = gw & 15;

    float* p = q + (long)row * DIMC + h * HDIM;
    float v0 = p[lane], v1 = p[lane + 32];
    float ss = v0 * v0 + v1 * v1;
#pragma unroll
    for (int o = 16; o; o >>= 1) ss += __shfl_xor_sync(0xffffffffu, ss, o);
    float inv = rsqrtf(ss * (1.f / 64.f) + 1e-6f);

    float q0 = v0 * inv * w[lane];
    float q1 = v1 * inv * w[lane + 32];

    int n = row & (NQ - 1);
    float c0 = cs[n * HDIM + lane],      s0 = sn[n * HDIM + lane];
    float c1 = cs[n * HDIM + lane + 32], s1 = sn[n * HDIM + lane + 32];
    p[lane]      = tf32f(q0 * c0 - q1 * s0);
    p[lane + 32] = tf32f(q1 * c1 + q0 * s1);
}

__global__ __launch_bounds__(256) void rmsnorm_k(
    float* __restrict__ k, const float* __restrict__ w)
{
    int gw   = (blockIdx.x * blockDim.x + threadIdx.x) >> 5;
    int lane = threadIdx.x & 31;
    int row  = gw >> 4;
    int h    = gw & 15;

    float* p = k + (long)row * DIMC + h * HDIM;
    float v0 = p[lane], v1 = p[lane + 32];
    float ss = v0 * v0 + v1 * v1;
#pragma unroll
    for (int o = 16; o; o >>= 1) ss += __shfl_xor_sync(0xffffffffu, ss, o);
    float inv = rsqrtf(ss * (1.f / 64.f) + 1e-6f);
    p[lane]      = tf32f(v0 * inv * w[lane]);
    p[lane + 32] = tf32f(v1 * inv * w[lane + 32]);
}

// ===========================================================================
// Register-resident tensor-core attention.
// CTA = 128 q-rows x 1 head x 1 batch; 8 warps; warp w owns q rows
// [16w,16w+16) x ALL 256 ctx. Scores live in registers end-to-end:
//   QK^T -> acc[32][4]; softmax with quad-shuffles (each row on 4 lanes);
//   P -> PV a-frags via lane shuffles; V b-frags via conflict-free scalar LDS.
// smem: Qs[128][68] | Ks[256][68] | Vs[256][68]; ONE __syncthreads total.
// ===========================================================================
#define ATQ 0
#define ATK (128 * 68)
#define ATV (ATK + 256 * 68)
#define ATT_FLOATS (ATV + 256 * 68)      // 43520 floats = 174080 B

__global__ __launch_bounds__(256) void attn_mma(
    const float* __restrict__ q, const float* __restrict__ k,
    const float* __restrict__ v, float* __restrict__ ao)
{
    extern __shared__ float sm[];
    float* Qs = sm + ATQ;
    float* Ks = sm + ATK;
    float* Vs = sm + ATV;
    const unsigned shu  = (unsigned)__cvta_generic_to_shared(sm);
    const unsigned qs_u = shu;
    const unsigned ks_u = shu + ATK * 4;

    const int t  = threadIdx.x;
    const int nt = blockIdx.x, h = blockIdx.y, b = blockIdx.z;
    const int qrow0  = b * NQ + nt * 128;
    const int kvrow0 = b * NCTX;
    const int cbase  = h * HDIM;

    // Q [128][68] (tf32-rounded by rmsnorm)
    for (int i4 = t; i4 < 128 * 16; i4 += 256) {
        int i = i4 >> 4, d4 = (i4 & 15) << 2;
        *(float4*)&Qs[i * 68 + d4] =
            *(const float4*)&q[(long)(qrow0 + i) * DIMC + cbase + d4];
    }
    // K [256][68]
    for (int i4 = t; i4 < 256 * 16; i4 += 256) {
        int j = i4 >> 4, d4 = (i4 & 15) << 2;
        *(float4*)&Ks[j * 68 + d4] =
            *(const float4*)&k[(long)(kvrow0 + j) * DIMC + cbase + d4];
    }
    // V [256][68] (tf32-rounded by KV-GEMM epilogue)
    for (int i4 = t; i4 < 256 * 16; i4 += 256) {
        int j = i4 >> 4, d4 = (i4 & 15) << 2;
        *(float4*)&Vs[j * 68 + d4] =
            *(const float4*)&v[(long)(kvrow0 + j) * DIMC + cbase + d4];
    }
    __syncthreads();   // the only CTA barrier

    const int lane = t & 31;
    const int w    = t >> 5;
    const int qr   = w * 16;

    const int aSel = ((lane >> 3) & 1) * 8 + (lane & 7);
    const int cSel = (lane >> 4) * 4;
    const int bRowSel = (lane >> 4) * 8 + (lane & 7);
    const int bColSel = ((lane >> 3) & 1) * 4;

    // ---- S = Q K^T  (16 x 256 per warp, in registers) --------------------
    float acc[32][4];
#pragma unroll
    for (int n = 0; n < 32; n++)
#pragma unroll
        for (int i = 0; i < 4; i++) acc[n][i] = 0.f;

#pragma unroll
    for (int ks = 0; ks < 8; ks++) {
        int d0 = ks * 8;
        unsigned a0, a1, a2, a3;
        LDSM4(a0, a1, a2, a3,
              qs_u + (unsigned)((qr + aSel) * 68 + d0 + cSel) * 4);
#pragma unroll
        for (int p = 0; p < 16; p++) {   // covers ctx n-tiles 2p, 2p+1
            unsigned b0, b1, b2, b3;
            LDSM4(b0, b1, b2, b3,
                  ks_u + (unsigned)((p * 16 + bRowSel) * 68 + d0 + bColSel) * 4);
            MMA_TF32(acc[2 * p],     a0, a1, a2, a3, b0, b1);
            MMA_TF32(acc[2 * p + 1], a0, a1, a2, a3, b2, b3);
        }
    }

    // ---- softmax (rows on lane-quads; regs c0,c1 = row lane>>2; c2,c3 = +8)
    const float scale = 0.125f;
    float mxA = -1e30f, mxB = -1e30f;
#pragma unroll
    for (int n = 0; n < 32; n++) {
        mxA = fmaxf(mxA, fmaxf(acc[n][0], acc[n][1]));
        mxB = fmaxf(mxB, fmaxf(acc[n][2], acc[n][3]));
    }
    mxA = fmaxf(mxA, __shfl_xor_sync(0xffffffffu, mxA, 1));
    mxA = fmaxf(mxA, __shfl_xor_sync(0xffffffffu, mxA, 2));
    mxB = fmaxf(mxB, __shfl_xor_sync(0xffffffffu, mxB, 1));
    mxB = fmaxf(mxB, __shfl_xor_sync(0xffffffffu, mxB, 2));
    mxA *= scale; mxB *= scale;

    float sA = 0.f, sB = 0.f;
#pragma unroll
    for (int n = 0; n < 32; n++) {
        acc[n][0] = __expf(acc[n][0] * scale - mxA); sA += acc[n][0];
        acc[n][1] = __expf(acc[n][1] * scale - mxA); sA += acc[n][1];
        acc[n][2] = __expf(acc[n][2] * scale - mxB); sB += acc[n][2];
        acc[n][3] = __expf(acc[n][3] * scale - mxB); sB += acc[n][3];
    }
    sA += __shfl_xor_sync(0xffffffffu, sA, 1);
    sA += __shfl_xor_sync(0xffffffffu, sA, 2);
    sB += __shfl_xor_sync(0xffffffffu, sB, 1);
    sB += __shfl_xor_sync(0xffffffffu, sB, 2);
    float invA = 1.f / sA, invB = 1.f / sB;
#pragma unroll
    for (int n = 0; n < 32; n++) {
        acc[n][0] = tf32f(acc[n][0] * invA);
        acc[n][1] = tf32f(acc[n][1] * invA);
        acc[n][2] = tf32f(acc[n][2] * invB);
        acc[n][3] = tf32f(acc[n][3] * invB);
    }

    // ---- O = P V  (P a-frags via shuffles; V b-frags via scalar LDS) -----
    // acc layout: P[row][col 2c,2c+1]; a-frag needs cols {c, 4+c} of tile.
    const int src1 = (lane & ~3) | ((lane & 3) >> 1);
    const int src2 = src1 + 2;
    const bool odd = lane & 1;

    float oacc[8][4];
#pragma unroll
    for (int dt = 0; dt < 8; dt++)
#pragma unroll
        for (int i = 0; i < 4; i++) oacc[dt][i] = 0.f;

#pragma unroll
    for (int ks = 0; ks < 32; ks++) {
        int j0 = ks * 8;
        float v00 = __shfl_sync(0xffffffffu, acc[ks][0], src1);
        float v01 = __shfl_sync(0xffffffffu, acc[ks][1], src1);
        float v02 = __shfl_sync(0xffffffffu, acc[ks][2], src1);
        float v03 = __shfl_sync(0xffffffffu, acc[ks][3], src1);
        float w00 = __shfl_sync(0xffffffffu, acc[ks][0], src2);
        float w01 = __shfl_sync(0xffffffffu, acc[ks][1], src2);
        float w02 = __shfl_sync(0xffffffffu, acc[ks][2], src2);
        float w03 = __shfl_sync(0xffffffffu, acc[ks][3], src2);
        unsigned a0 = __float_as_uint(odd ? v01 : v00);
        unsigned a1 = __float_as_uint(odd ? v03 : v02);
        unsigned a2 = __float_as_uint(odd ? w01 : w00);
        unsigned a3 = __float_as_uint(odd ? w03 : w02);

        // b-frags: b0 = V[j0+(lane&3)][8*dt+(lane>>2)], b1 = +4 rows
        int vb0 = (j0 + (lane & 3)) * 68 + (lane >> 2);
        int vb1 = vb0 + 4 * 68;
#pragma unroll
        for (int dt = 0; dt < 8; dt++) {
            unsigned b0 = __float_as_uint(Vs[vb0 + dt * 8]);
            unsigned b1 = __float_as_uint(Vs[vb1 + dt * 8]);
            MMA_TF32(oacc[dt], a0, a1, a2, a3, b0, b1);
        }
    }

    // store O (tf32-rounded; feeds O-proj GEMM)
#pragma unroll
    for (int dt = 0; dt < 8; dt++) {
        long row = qrow0 + qr + (lane >> 2);
        int  col = cbase + dt * 8 + 2 * (lane & 3);
        float2 r0, r1;
        r0.x = tf32f(oacc[dt][0]); r0.y = tf32f(oacc[dt][1]);
        r1.x = tf32f(oacc[dt][2]); r1.y = tf32f(oacc[dt][3]);
        *(float2*)&ao[row * DIMC + col]       = r0;
        *(float2*)&ao[(row + 8) * DIMC + col] = r1;
    }
}

// ---------------------------------------------------------------------------
extern "C" void kernel_launch(void* const* d_in, const int* in_sizes, int n_in,
                              void* d_out, int out_size)
{
    const float* x  = (const float*)d_in[0];
    const float* c  = (const float*)d_in[1];
    const float* rc = (const float*)d_in[2];
    const float* rs = (const float*)d_in[3];
    const float* Wq = (const float*)d_in[4];
    const float* Wk = (const float*)d_in[5];
    const float* Wv = (const float*)d_in[6];
    const float* Wo = (const float*)d_in[7];
    const float* bo = (const float*)d_in[8];
    const float* qw = (const float*)d_in[9];
    const float* kw = (const float*)d_in[10];
    float* out = (float*)d_out;

    float *q, *k, *v, *ao, *xr, *cr, *wt;
    cudaGetSymbolAddress((void**)&q,  g_q);
    cudaGetSymbolAddress((void**)&k,  g_k);
    cudaGetSymbolAddress((void**)&v,  g_v);
    cudaGetSymbolAddress((void**)&ao, g_ao);
    cudaGetSymbolAddress((void**)&xr, g_xr);
    cudaGetSymbolAddress((void**)&cr, g_cr);
    cudaGetSymbolAddress((void**)&wt, g_wt);

    cudaFuncSetAttribute(gemm_tf32, cudaFuncAttributeMaxDynamicSharedMemorySize,
                         GEMM_SMEM);
    cudaFuncSetAttribute(attn_mma, cudaFuncAttributeMaxDynamicSharedMemorySize,
                         ATT_FLOATS * (int)sizeof(float));

    // ---- prep: round activations, transpose+round weights ----------------
    {
        int n4x = BATCH * NQ * DIMC / 4;
        round_tf32<<<n4x / 256, 256>>>(x, xr, n4x);
        int n4c = BATCH * NCTX * DIMC / 4;
        round_tf32<<<n4c / 256, 256>>>(c, cr, n4c);
        trans_round_w<<<dim3(32, 32, 4), 256>>>(Wq, Wk, Wv, Wo, wt);
    }
    const float* wqt = wt;
    const float* wkt = wt + (long)1 * DIMC * DIMC;
    const float* wvt = wt + (long)2 * DIMC * DIMC;
    const float* wot = wt + (long)3 * DIMC * DIMC;

    // ---- projections (K/V outputs tf32-rounded for attention) ------------
    gemm_tf32<<<dim3(8, 128, 1), 256, GEMM_SMEM>>>(
        xr, wqt, wqt, nullptr, q, q, BATCH * NQ, DIMC, DIMC, 0);
    gemm_tf32<<<dim3(8, 8, 2), 256, GEMM_SMEM>>>(
        cr, wkt, wvt, nullptr, k, v, BATCH * NCTX, DIMC, DIMC, 1);

    // ---- norms (+RoPE on Q) ----------------------------------------------
    rmsnorm_rope_q<<<(BATCH * NQ * NHEADS) / 8, 256>>>(q, rc, rs, qw);
    rmsnorm_k<<<(BATCH * NCTX * NHEADS) / 8, 256>>>(k, kw);

    // ---- attention (register-resident flash) -----------------------------
    attn_mma<<<dim3(NQ / 128, NHEADS, BATCH), 256,
               ATT_FLOATS * (int)sizeof(float)>>>(q, k, v, ao);

    // ---- output projection + bias ----------------------------------------
    gemm_tf32<<<dim3(8, 128, 1), 256, GEMM_SMEM>>>(
        ao, wot, wot, bo, out, out, BATCH * NQ, DIMC, DIMC, 0);
}

// round 15
// speedup vs baseline: 1.6765x; 1.0006x over previous
#include <cuda_runtime.h>
#include <math.h>

#define DIMC   1024
#define NHEADS 16
#define HDIM   64
#define BATCH  4
#define NQ     4096
#define NCTX   256

// Scratch (no allocations allowed) ------------------------------------------
__device__ float g_q [BATCH * NQ   * DIMC];   // 64 MB (normed+roped, tf32)
__device__ float g_k [BATCH * NCTX * DIMC];   //  4 MB (normed, tf32)
__device__ float g_v [BATCH * NCTX * DIMC];   //  4 MB (tf32)
__device__ float g_ao[BATCH * NQ   * DIMC];   // 64 MB
__device__ float g_xr[BATCH * NQ   * DIMC];   // 64 MB  x pre-rounded tf32
__device__ float g_cr[BATCH * NCTX * DIMC];   //  4 MB  c pre-rounded
__device__ float g_wt[4][DIMC * DIMC];        // 16 MB  W^T, tf32-rounded

__device__ __forceinline__ float tf32f(float f) {
    unsigned r;
    asm("cvt.rna.tf32.f32 %0, %1;" : "=r"(r) : "f"(f));
    return __uint_as_float(r);
}

#define MMA_TF32(C, a0, a1, a2, a3, b0, b1)                                   \
    asm volatile(                                                             \
        "mma.sync.aligned.m16n8k8.row.col.f32.tf32.tf32.f32 "                 \
        "{%0,%1,%2,%3}, {%4,%5,%6,%7}, {%8,%9}, {%0,%1,%2,%3};"               \
        : "+f"((C)[0]), "+f"((C)[1]), "+f"((C)[2]), "+f"((C)[3])              \
        : "r"(a0), "r"(a1), "r"(a2), "r"(a3), "r"(b0), "r"(b1))

#define LDSM4(r0, r1, r2, r3, saddr)                                          \
    asm volatile("ldmatrix.sync.aligned.m8n8.x4.shared.b16 {%0,%1,%2,%3}, [%4];" \
        : "=r"(r0), "=r"(r1), "=r"(r2), "=r"(r3) : "r"(saddr))

#define CPA16(saddr, gptr) \
    asm volatile("cp.async.cg.shared.global [%0], [%1], 16;" :: "r"(saddr), "l"(gptr))

// ===========================================================================
// Prep kernels
// ===========================================================================
__global__ __launch_bounds__(256) void round_tf32(
    const float* __restrict__ s, float* __restrict__ d, int n4)
{
    int i = blockIdx.x * blockDim.x + threadIdx.x;
    if (i < n4) {
        float4 v = ((const float4*)s)[i];
        v.x = tf32f(v.x); v.y = tf32f(v.y);
        v.z = tf32f(v.z); v.w = tf32f(v.w);
        ((float4*)d)[i] = v;
    }
}

__global__ __launch_bounds__(256) void trans_round_w(
    const float* __restrict__ s0, const float* __restrict__ s1,
    const float* __restrict__ s2, const float* __restrict__ s3,
    float* __restrict__ d)
{
    const float* s = (blockIdx.z == 0) ? s0 : (blockIdx.z == 1) ? s1
                   : (blockIdx.z == 2) ? s2 : s3;
    float* dd = d + (long)blockIdx.z * (DIMC * DIMC);
    __shared__ float t[32][33];
    int tx = threadIdx.x & 31, ty = threadIdx.x >> 5;
    int bx = blockIdx.x * 32, by = blockIdx.y * 32;
#pragma unroll
    for (int i = 0; i < 32; i += 8)
        t[ty + i][tx] = tf32f(s[(long)(by + ty + i) * DIMC + bx + tx]);
    __syncthreads();
#pragma unroll
    for (int i = 0; i < 32; i += 8)
        dd[(long)(bx + ty + i) * DIMC + by + tx] = t[tx][ty + i];
}

// ===========================================================================
// tf32 GEMM, B pre-transposed (k-major). 128x128x32 tile, 256 thr, ldmatrix.
// ONE __syncthreads per mainloop iteration (wait -> sync -> issue -> compute).
// Fused epilogues (selected per blockIdx.z):
//   mode 0: (+bias) (+tf32 round if roundC)
//   mode 1: per-head RMSNorm * nw, tf32 round      (K path)
//   mode 2: per-head RMSNorm * nw + RoPE, tf32 round (Q path)
// ===========================================================================
#define AST 36
#define STAGE_F (2 * 128 * AST)
#define STAGE_B (STAGE_F * 4)
#define GEMM_SMEM (2 * STAGE_B)          // 73728 B (also covers epilogue bufs)

__global__ __launch_bounds__(256) void gemm_tf32(
    const float* __restrict__ A,
    const float* __restrict__ Bt0, const float* __restrict__ Bt1,
    const float* __restrict__ bias,
    const float* __restrict__ nw0, const float* __restrict__ nw1,
    const float* __restrict__ rcos, const float* __restrict__ rsin,
    float* __restrict__ C0, float* __restrict__ C1,
    int M, int N, int K,
    int mode0, int mode1, int round0, int round1)
{
    extern __shared__ float sh[];
    const int z = blockIdx.z;
    const float* Bt = z ? Bt1 : Bt0;
    float*       C  = z ? C1  : C0;
    const float* nw = z ? nw1 : nw0;
    const int mode   = z ? mode1  : mode0;
    const int roundC = z ? round1 : round0;

    const int t    = threadIdx.x;
    const int lane = t & 31;
    const int w    = t >> 5;
    const int wm   = (w & 1) * 64;
    const int wn   = (w >> 1) * 32;
    const int m0   = blockIdx.y * 128;
    const int n0   = blockIdx.x * 128;

    const unsigned shu = (unsigned)__cvta_generic_to_shared(sh);

    float acc[4][4][4];
#pragma unroll
    for (int mt = 0; mt < 4; mt++)
#pragma unroll
        for (int nt = 0; nt < 4; nt++)
#pragma unroll
            for (int i = 0; i < 4; i++) acc[mt][nt][i] = 0.f;

#define ISSUE(s, k0)                                                          \
    {                                                                         \
        unsigned abase = shu + (s) * STAGE_B;                                 \
        unsigned bbase = abase + 128 * AST * 4;                               \
        _Pragma("unroll")                                                     \
        for (int j = 0; j < 4; j++) {                                         \
            int idx = t + j * 256;                                            \
            int r = idx >> 3, c4 = (idx & 7) << 2;                            \
            CPA16(abase + (unsigned)(r * AST + c4) * 4,                       \
                  A + (long)(m0 + r) * K + (k0) + c4);                        \
            CPA16(bbase + (unsigned)(r * AST + c4) * 4,                       \
                  Bt + (long)(n0 + r) * K + (k0) + c4);                       \
        }                                                                     \
        asm volatile("cp.async.commit_group;");                               \
    }

    const int aSel = ((lane >> 3) & 1) * 8 + (lane & 7);
    const int cSel = (lane >> 4) * 4;
    const int bRowSel = (lane >> 4) * 8 + (lane & 7);
    const int bColSel = ((lane >> 3) & 1) * 4;

    const int niter = K >> 5;
    ISSUE(0, 0);

    for (int it = 0; it < niter; it++) {
        asm volatile("cp.async.wait_group 0;");
        __syncthreads();                       // data ready + prev reads done
        if (it + 1 < niter) ISSUE((it + 1) & 1, (it + 1) << 5);

        unsigned as_u = shu + (it & 1) * STAGE_B;
        unsigned bs_u = as_u + 128 * AST * 4;

#pragma unroll
        for (int kk = 0; kk < 32; kk += 8) {
            unsigned af[4][4], bf[4][2];
#pragma unroll
            for (int mt = 0; mt < 4; mt++) {
                unsigned ad = as_u +
                    (unsigned)((wm + mt * 16 + aSel) * AST + kk + cSel) * 4;
                LDSM4(af[mt][0], af[mt][1], af[mt][2], af[mt][3], ad);
            }
#pragma unroll
            for (int p = 0; p < 2; p++) {
                unsigned bd = bs_u +
                    (unsigned)((wn + p * 16 + bRowSel) * AST + kk + bColSel) * 4;
                LDSM4(bf[2 * p][0], bf[2 * p][1], bf[2 * p + 1][0],
                      bf[2 * p + 1][1], bd);
            }
#pragma unroll
            for (int mt = 0; mt < 4; mt++)
#pragma unroll
                for (int nt = 0; nt < 4; nt++)
                    MMA_TF32(acc[mt][nt], af[mt][0], af[mt][1], af[mt][2],
                             af[mt][3], bf[nt][0], bf[nt][1]);
        }
        __syncthreads();                       // all reads of this stage done
    }

    const int qrow = lane >> 2;

    if (mode == 0) {
        // ---- plain epilogue: bias + optional round -----------------------
#pragma unroll
        for (int nt = 0; nt < 4; nt++) {
            int col = n0 + wn + nt * 8 + 2 * (lane & 3);
            float bb0 = bias ? bias[col]     : 0.f;
            float bb1 = bias ? bias[col + 1] : 0.f;
#pragma unroll
            for (int mt = 0; mt < 4; mt++) {
                int row = m0 + wm + mt * 16 + qrow;
                float2 r0, r1;
                r0.x = acc[mt][nt][0] + bb0; r0.y = acc[mt][nt][1] + bb1;
                r1.x = acc[mt][nt][2] + bb0; r1.y = acc[mt][nt][3] + bb1;
                if (roundC) {
                    r0.x = tf32f(r0.x); r0.y = tf32f(r0.y);
                    r1.x = tf32f(r1.x); r1.y = tf32f(r1.y);
                }
                *(float2*)&C[(long)row * N + col]       = r0;
                *(float2*)&C[(long)(row + 8) * N + col] = r1;
            }
        }
    } else {
        // ---- fused RMSNorm (+RoPE) epilogue ------------------------------
        float* ssb = sh;                 // [2 ny-slots? -> 4][128]
        float* vt  = sh + 512;           // [128][132] (mode 2 only)
        const int ny = w >> 1;

        float ssA[4], ssB[4];
#pragma unroll
        for (int mt = 0; mt < 4; mt++) {
            float a = 0.f, b2 = 0.f;
#pragma unroll
            for (int nt = 0; nt < 4; nt++) {
                a  += acc[mt][nt][0] * acc[mt][nt][0]
                    + acc[mt][nt][1] * acc[mt][nt][1];
                b2 += acc[mt][nt][2] * acc[mt][nt][2]
                    + acc[mt][nt][3] * acc[mt][nt][3];
            }
            a  += __shfl_xor_sync(0xffffffffu, a, 1);
            a  += __shfl_xor_sync(0xffffffffu, a, 2);
            b2 += __shfl_xor_sync(0xffffffffu, b2, 1);
            b2 += __shfl_xor_sync(0xffffffffu, b2, 2);
            ssA[mt] = a; ssB[mt] = b2;
        }
        if ((lane & 3) == 0) {
#pragma unroll
            for (int mt = 0; mt < 4; mt++) {
                int rl = wm + 16 * mt + qrow;
                ssb[ny * 128 + rl]     = ssA[mt];
                ssb[ny * 128 + rl + 8] = ssB[mt];
            }
        }
        __syncthreads();

#pragma unroll
        for (int mt = 0; mt < 4; mt++) {
            int rl = wm + 16 * mt + qrow;
            float invA = rsqrtf((ssA[mt] + ssb[(ny ^ 1) * 128 + rl])
                                * (1.f / 64.f) + 1e-6f);
            float invB = rsqrtf((ssB[mt] + ssb[(ny ^ 1) * 128 + rl + 8])
                                * (1.f / 64.f) + 1e-6f);
#pragma unroll
            for (int nt = 0; nt < 4; nt++) {
                int cl = wn + nt * 8 + 2 * (lane & 3);
                float w0 = nw[cl & 63], w1 = nw[(cl + 1) & 63];
                acc[mt][nt][0] *= invA * w0;
                acc[mt][nt][1] *= invA * w1;
                acc[mt][nt][2] *= invB * w0;
                acc[mt][nt][3] *= invB * w1;
            }
        }

        if (mode == 1) {
            // K path: store normed, tf32-rounded
#pragma unroll
            for (int mt = 0; mt < 4; mt++) {
                int row = m0 + wm + 16 * mt + qrow;
#pragma unroll
                for (int nt = 0; nt < 4; nt++) {
                    int col = n0 + wn + nt * 8 + 2 * (lane & 3);
                    *(float2*)&C[(long)row * N + col] =
                        make_float2(tf32f(acc[mt][nt][0]), tf32f(acc[mt][nt][1]));
                    *(float2*)&C[(long)(row + 8) * N + col] =
                        make_float2(tf32f(acc[mt][nt][2]), tf32f(acc[mt][nt][3]));
                }
            }
        } else {
            // Q path: RoPE needs the d^32 partner -> exchange via smem tile
#pragma unroll
            for (int mt = 0; mt < 4; mt++) {
                int rl = wm + 16 * mt + qrow;
#pragma unroll
                for (int nt = 0; nt < 4; nt++) {
                    int cl = wn + nt * 8 + 2 * (lane & 3);
                    *(float2*)&vt[rl * 132 + cl] =
                        make_float2(acc[mt][nt][0], acc[mt][nt][1]);
                    *(float2*)&vt[(rl + 8) * 132 + cl] =
                        make_float2(acc[mt][nt][2], acc[mt][nt][3]);
                }
            }
            __syncthreads();
#pragma unroll
            for (int mt = 0; mt < 4; mt++) {
                int rl = wm + 16 * mt + qrow;
                int nA = (m0 + rl)     & (NQ - 1);
                int nB = (m0 + rl + 8) & (NQ - 1);
#pragma unroll
                for (int nt = 0; nt < 4; nt++) {
                    int cl = wn + nt * 8 + 2 * (lane & 3);
                    int d  = cl & 63;
                    float2 cA = *(const float2*)&rcos[nA * 64 + d];
                    float2 sA = *(const float2*)&rsin[nA * 64 + d];
                    float2 cB = *(const float2*)&rcos[nB * 64 + d];
                    float2 sB = *(const float2*)&rsin[nB * 64 + d];
                    float p0A = vt[rl * 132 + (cl ^ 32)];
                    float p1A = vt[rl * 132 + ((cl + 1) ^ 32)];
                    float p0B = vt[(rl + 8) * 132 + (cl ^ 32)];
                    float p1B = vt[(rl + 8) * 132 + ((cl + 1) ^ 32)];
                    float sgn = (cl & 32) ? 1.f : -1.f;  // d<32 -> -sin part
                    float o0A = acc[mt][nt][0] * cA.x + sgn * p0A * sA.x;
                    float o1A = acc[mt][nt][1] * cA.y + sgn * p1A * sA.y;
                    float o0B = acc[mt][nt][2] * cB.x + sgn * p0B * sB.x;
                    float o1B = acc[mt][nt][3] * cB.y + sgn * p1B * sB.y;
                    int row = m0 + rl, col = n0 + cl;
                    *(float2*)&C[(long)row * N + col] =
                        make_float2(tf32f(o0A), tf32f(o1A));
                    *(float2*)&C[(long)(row + 8) * N + col] =
                        make_float2(tf32f(o0B), tf32f(o1B));
                }
            }
        }
    }
}

// ===========================================================================
// Register-resident tensor-core attention.
// CTA = 128 q-rows x 1 head x 1 batch; 8 warps; warp w owns 16 q-rows x 256 ctx.
// QK^T -> acc regs; quad-shuffle softmax; PV via per-warp smem P buffers
// (aliased over dead Qs/Ks) + ldmatrix, V b-frags via conflict-free LDS.
// ===========================================================================
#define ATQ 0
#define ATK (128 * 68)
#define ATV (ATK + 256 * 68)
#define ATT_FLOATS (ATV + 256 * 68)      // 43520 floats = 174080 B
#define PSTR 132
#define PBUF_W (16 * PSTR)               // 2112 floats per warp (16 x 132)

__global__ __launch_bounds__(256) void attn_mma(
    const float* __restrict__ q, const float* __restrict__ k,
    const float* __restrict__ v, float* __restrict__ ao)
{
    extern __shared__ float sm[];
    float* Qs = sm + ATQ;
    float* Ks = sm + ATK;
    float* Vs = sm + ATV;
    const unsigned shu  = (unsigned)__cvta_generic_to_shared(sm);
    const unsigned qs_u = shu;
    const unsigned ks_u = shu + ATK * 4;

    const int t  = threadIdx.x;
    const int nt = blockIdx.x, h = blockIdx.y, b = blockIdx.z;
    const int qrow0  = b * NQ + nt * 128;
    const int kvrow0 = b * NCTX;
    const int cbase  = h * HDIM;

    for (int i4 = t; i4 < 128 * 16; i4 += 256) {
        int i = i4 >> 4, d4 = (i4 & 15) << 2;
        *(float4*)&Qs[i * 68 + d4] =
            *(const float4*)&q[(long)(qrow0 + i) * DIMC + cbase + d4];
    }
    for (int i4 = t; i4 < 256 * 16; i4 += 256) {
        int j = i4 >> 4, d4 = (i4 & 15) << 2;
        *(float4*)&Ks[j * 68 + d4] =
            *(const float4*)&k[(long)(kvrow0 + j) * DIMC + cbase + d4];
    }
    for (int i4 = t; i4 < 256 * 16; i4 += 256) {
        int j = i4 >> 4, d4 = (i4 & 15) << 2;
        *(float4*)&Vs[j * 68 + d4] =
            *(const float4*)&v[(long)(kvrow0 + j) * DIMC + cbase + d4];
    }
    __syncthreads();

    const int lane = t & 31;
    const int w    = t >> 5;
    const int qr   = w * 16;

    const int aSel = ((lane >> 3) & 1) * 8 + (lane & 7);
    const int cSel = (lane >> 4) * 4;
    const int bRowSel = (lane >> 4) * 8 + (lane & 7);
    const int bColSel = ((lane >> 3) & 1) * 4;

    // ---- S = Q K^T (16 x 256 per warp, in registers) ---------------------
    float acc[32][4];
#pragma unroll
    for (int n = 0; n < 32; n++)
#pragma unroll
        for (int i = 0; i < 4; i++) acc[n][i] = 0.f;

#pragma unroll
    for (int ks = 0; ks < 8; ks++) {
        int d0 = ks * 8;
        unsigned a0, a1, a2, a3;
        LDSM4(a0, a1, a2, a3,
              qs_u + (unsigned)((qr + aSel) * 68 + d0 + cSel) * 4);
#pragma unroll
        for (int p = 0; p < 16; p++) {
            unsigned b0, b1, b2, b3;
            LDSM4(b0, b1, b2, b3,
                  ks_u + (unsigned)((p * 16 + bRowSel) * 68 + d0 + bColSel) * 4);
            MMA_TF32(acc[2 * p],     a0, a1, a2, a3, b0, b1);
            MMA_TF32(acc[2 * p + 1], a0, a1, a2, a3, b2, b3);
        }
    }
    __syncthreads();   // Qs/Ks reads done (P buffers alias them)

    // ---- softmax (rows on lane-quads) ------------------------------------
    const float scale = 0.125f;
    float mxA = -1e30f, mxB = -1e30f;
#pragma unroll
    for (int n = 0; n < 32; n++) {
        mxA = fmaxf(mxA, fmaxf(acc[n][0], acc[n][1]));
        mxB = fmaxf(mxB, fmaxf(acc[n][2], acc[n][3]));
    }
    mxA = fmaxf(mxA, __shfl_xor_sync(0xffffffffu, mxA, 1));
    mxA = fmaxf(mxA, __shfl_xor_sync(0xffffffffu, mxA, 2));
    mxB = fmaxf(mxB, __shfl_xor_sync(0xffffffffu, mxB, 1));
    mxB = fmaxf(mxB, __shfl_xor_sync(0xffffffffu, mxB, 2));
    mxA *= scale; mxB *= scale;

    float sA = 0.f, sB = 0.f;
#pragma unroll
    for (int n = 0; n < 32; n++) {
        acc[n][0] = __expf(acc[n][0] * scale - mxA); sA += acc[n][0];
        acc[n][1] = __expf(acc[n][1] * scale - mxA); sA += acc[n][1];
        acc[n][2] = __expf(acc[n][2] * scale - mxB); sB += acc[n][2];
        acc[n][3] = __expf(acc[n][3] * scale - mxB); sB += acc[n][3];
    }
    sA += __shfl_xor_sync(0xffffffffu, sA, 1);
    sA += __shfl_xor_sync(0xffffffffu, sA, 2);
    sB += __shfl_xor_sync(0xffffffffu, sB, 1);
    sB += __shfl_xor_sync(0xffffffffu, sB, 2);
    float invA = 1.f / sA, invB = 1.f / sB;
#pragma unroll
    for (int n = 0; n < 32; n++) {
        acc[n][0] = tf32f(acc[n][0] * invA);
        acc[n][1] = tf32f(acc[n][1] * invA);
        acc[n][2] = tf32f(acc[n][2] * invB);
        acc[n][3] = tf32f(acc[n][3] * invB);
    }

    // ---- O = P V: per-warp smem P + ldmatrix a-frags ---------------------
    float* Pb = sm + w * PBUF_W;                     // aliases Qs/Ks
    const unsigned pb_u = shu + (unsigned)(w * PBUF_W) * 4;

    float oacc[8][4];
#pragma unroll
    for (int dt = 0; dt < 8; dt++)
#pragma unroll
        for (int i = 0; i < 4; i++) oacc[dt][i] = 0.f;

#pragma unroll
    for (int hf = 0; hf < 2; hf++) {
#pragma unroll
        for (int nl = 0; nl < 16; nl++) {
            int n = 16 * hf + nl;
            int base = (lane >> 2) * PSTR + nl * 8 + 2 * (lane & 3);
            *(float2*)&Pb[base]            = make_float2(acc[n][0], acc[n][1]);
            *(float2*)&Pb[base + 8 * PSTR] = make_float2(acc[n][2], acc[n][3]);
        }
        __syncwarp();
#pragma unroll
        for (int ksl = 0; ksl < 16; ksl++) {
            unsigned a0, a1, a2, a3;
            LDSM4(a0, a1, a2, a3,
                  pb_u + (unsigned)(aSel * PSTR + ksl * 8 + cSel) * 4);
            int j0 = 128 * hf + ksl * 8;
            int vb0 = (j0 + (lane & 3)) * 68 + (lane >> 2);
            int vb1 = vb0 + 4 * 68;
#pragma unroll
            for (int dt = 0; dt < 8; dt++) {
                unsigned b0 = __float_as_uint(Vs[vb0 + dt * 8]);
                unsigned b1 = __float_as_uint(Vs[vb1 + dt * 8]);
                MMA_TF32(oacc[dt], a0, a1, a2, a3, b0, b1);
            }
        }
        __syncwarp();   // P reads done before next half overwrites
    }

    // store O (tf32-rounded; feeds O-proj GEMM)
#pragma unroll
    for (int dt = 0; dt < 8; dt++) {
        long row = qrow0 + qr + (lane >> 2);
        int  col = cbase + dt * 8 + 2 * (lane & 3);
        float2 r0, r1;
        r0.x = tf32f(oacc[dt][0]); r0.y = tf32f(oacc[dt][1]);
        r1.x = tf32f(oacc[dt][2]); r1.y = tf32f(oacc[dt][3]);
        *(float2*)&ao[row * DIMC + col]       = r0;
        *(float2*)&ao[(row + 8) * DIMC + col] = r1;
    }
}

// ---------------------------------------------------------------------------
extern "C" void kernel_launch(void* const* d_in, const int* in_sizes, int n_in,
                              void* d_out, int out_size)
{
    const float* x  = (const float*)d_in[0];
    const float* c  = (const float*)d_in[1];
    const float* rc = (const float*)d_in[2];
    const float* rs = (const float*)d_in[3];
    const float* Wq = (const float*)d_in[4];
    const float* Wk = (const float*)d_in[5];
    const float* Wv = (const float*)d_in[6];
    const float* Wo = (const float*)d_in[7];
    const float* bo = (const float*)d_in[8];
    const float* qw = (const float*)d_in[9];
    const float* kw = (const float*)d_in[10];
    float* out = (float*)d_out;

    float *q, *k, *v, *ao, *xr, *cr, *wt;
    cudaGetSymbolAddress((void**)&q,  g_q);
    cudaGetSymbolAddress((void**)&k,  g_k);
    cudaGetSymbolAddress((void**)&v,  g_v);
    cudaGetSymbolAddress((void**)&ao, g_ao);
    cudaGetSymbolAddress((void**)&xr, g_xr);
    cudaGetSymbolAddress((void**)&cr, g_cr);
    cudaGetSymbolAddress((void**)&wt, g_wt);

    cudaFuncSetAttribute(gemm_tf32, cudaFuncAttributeMaxDynamicSharedMemorySize,
                         GEMM_SMEM);
    cudaFuncSetAttribute(attn_mma, cudaFuncAttributeMaxDynamicSharedMemorySize,
                         ATT_FLOATS * (int)sizeof(float));

    // ---- prep: round activations, transpose+round weights ----------------
    {
        int n4x = BATCH * NQ * DIMC / 4;
        round_tf32<<<n4x / 256, 256>>>(x, xr, n4x);
        int n4c = BATCH * NCTX * DIMC / 4;
        round_tf32<<<n4c / 256, 256>>>(c, cr, n4c);
        trans_round_w<<<dim3(32, 32, 4), 256>>>(Wq, Wk, Wv, Wo, wt);
    }
    const float* wqt = wt;
    const float* wkt = wt + (long)1 * DIMC * DIMC;
    const float* wvt = wt + (long)2 * DIMC * DIMC;
    const float* wot = wt + (long)3 * DIMC * DIMC;

    // ---- Q projection + fused RMSNorm + RoPE (mode 2) --------------------
    gemm_tf32<<<dim3(8, 128, 1), 256, GEMM_SMEM>>>(
        xr, wqt, wqt, nullptr, qw, qw, rc, rs,
        q, q, BATCH * NQ, DIMC, DIMC, 2, 2, 1, 1);

    // ---- K (mode 1: fused RMSNorm) and V (mode 0 + round) ----------------
    gemm_tf32<<<dim3(8, 8, 2), 256, GEMM_SMEM>>>(
        cr, wkt, wvt, nullptr, kw, nullptr, nullptr, nullptr,
        k, v, BATCH * NCTX, DIMC, DIMC, 1, 0, 1, 1);

    // ---- attention --------------------------------------------------------
    attn_mma<<<dim3(NQ / 128, NHEADS, BATCH), 256,
               ATT_FLOATS * (int)sizeof(float)>>>(q, k, v, ao);

    // ---- output projection + bias (mode 0) -------------------------------
    gemm_tf32<<<dim3(8, 128, 1), 256, GEMM_SMEM>>>(
        ao, wot, wot, bo, nullptr, nullptr, nullptr, nullptr,
        out, out, BATCH * NQ, DIMC, DIMC, 0, 0, 0, 0);
}